// round 14
// baseline (speedup 1.0000x reference)
#include <cuda_runtime.h>
#include <cuda_bf16.h>
#include <cstdint>
#include <cstddef>

#define NL 6
#define NH 16
#define CD 1024
#define HSD 64
#define FFD 4096
#define NV 67
#define NB 8
#define NT 1024
#define NM (NB*NT)   // 8192 rows

typedef unsigned long long u64;
typedef unsigned int u32;

// Arch-specific feature gate: tcgen05 only exists in the sm_103a cubin pass.
#if defined(__CUDA_ARCH__) && (defined(__CUDA_ARCH_FEAT_SM103_ALL) || defined(__CUDA_ARCH_SPECIFIC__))
#define HAS_TCGEN05 1
#else
#define HAS_TCGEN05 0
#endif

// weight segment layout (elements): QKV@0 (3M), Wo@3M (1M), W1@4M (4M), W2@8M (4M)
#define WSEG  12582912ull            // 12M elements per layer-parity segment
#define WOFF_QKV 0ull
#define WOFF_WO  3145728ull
#define WOFF_W1  4194304ull
#define WOFF_W2  8388608ull

// ------------------------- scratch (device globals, no allocation) ---------
__device__ float g_x [(size_t)NM*CD];
__device__ float g_h [(size_t)NM*CD];
__device__ float g_q [(size_t)NM*CD];
__device__ float g_k [(size_t)NM*CD];
__device__ float g_v [(size_t)NM*CD];
// bf16 split buffers: two activation pairs (ping/pong) + double-buffered weights
__device__ __nv_bfloat16 g_ah[(size_t)NM*FFD];
__device__ __nv_bfloat16 g_al[(size_t)NM*FFD];
__device__ __nv_bfloat16 g_bh[(size_t)NM*FFD];
__device__ __nv_bfloat16 g_bl[(size_t)NM*FFD];
__device__ __nv_bfloat16 g_wh[2*WSEG];
__device__ __nv_bfloat16 g_wl[2*WSEG];

__device__ __forceinline__ float* buf(int which) {
    switch (which) {
        case 0: return g_x;
        case 1: return g_h;
        case 2: return g_q;
        case 3: return g_k;
        default: return g_v;
    }
}

// ------------------------- PTX helpers -------------------------------------
__device__ __forceinline__ u32 smem_u32(const void* p) {
    u32 a;
    asm("{ .reg .u64 t; cvta.to.shared.u64 t, %1; cvt.u32.u64 %0, t; }"
        : "=r"(a) : "l"(p));
    return a;
}
#define SWZ64(o)  ((o) ^ (((o) >> 3) & 0x30))
#define SWZ128(o) ((o) ^ (((o) >> 3) & 0x70))

#define CP_ASYNC16(dst, src) \
    asm volatile("cp.async.cg.shared.global [%0], [%1], 16;" \
                 :: "r"(dst), "l"(src) : "memory")
#define CP_COMMIT() asm volatile("cp.async.commit_group;" ::: "memory")
#define CP_WAIT0()  asm volatile("cp.async.wait_group 0;" ::: "memory")
#define CP_WAIT1()  asm volatile("cp.async.wait_group 1;" ::: "memory")

#define STS16(addr, v) \
    asm volatile("st.shared.u16 [%0], %1;" :: "r"(addr), "h"(v) : "memory")

#define CLUSTER_SYNC() do { \
    asm volatile("barrier.cluster.arrive.aligned;" ::: "memory"); \
    asm volatile("barrier.cluster.wait.aligned;" ::: "memory"); \
} while (0)

__device__ __forceinline__ void sts128(u32 addr, uint4 v) {
    asm volatile("st.shared.v4.b32 [%0], {%1,%2,%3,%4};"
                 :: "r"(addr), "r"(v.x), "r"(v.y), "r"(v.z), "r"(v.w) : "memory");
}

__device__ __forceinline__ u32 packbf2(float a, float b) {
    __nv_bfloat162 t(__float2bfloat16(a), __float2bfloat16(b));
    return *(u32*)&t;
}

__device__ __forceinline__ void mbar_init(u32 addr, u32 cnt) {
    asm volatile("mbarrier.init.shared.b64 [%0], %1;" :: "r"(addr), "r"(cnt) : "memory");
}
__device__ __forceinline__ void mbar_wait(u32 addr, u32 phase) {
    asm volatile("{\n\t.reg .pred P;\n\t"
        "W_%=:\n\t"
        "mbarrier.try_wait.parity.acquire.cta.shared::cta.b64 P, [%0], %1, 0x989680;\n\t"
        "@P bra.uni D_%=;\n\t"
        "bra.uni W_%=;\n\t"
        "D_%=:\n\t}"
        :: "r"(addr), "r"(phase) : "memory");
}

#if HAS_TCGEN05
__device__ __forceinline__ u32 elect1() {
    u32 pred;
    asm volatile("{\n\t.reg .pred p;\n\telect.sync _|p, 0xFFFFFFFF;\n\t"
                 "selp.b32 %0, 1, 0, p;\n\t}" : "=r"(pred));
    return pred;
}
__device__ __forceinline__ void mma_f16_ss(u32 d, u64 ad, u64 bd, u32 idesc, u32 acc) {
    asm volatile("{\n\t.reg .pred p;\n\tsetp.ne.u32 p, %5, 0;\n\t"
        "tcgen05.mma.cta_group::1.kind::f16 [%0], %1, %2, %3, {%4,%4,%4,%4}, p;\n\t}"
        :: "r"(d), "l"(ad), "l"(bd), "r"(idesc), "r"(0u), "r"(acc) : "memory");
}
__device__ __forceinline__ void mma_f16_ts(u32 d, u32 a, u64 bd, u32 idesc, u32 acc) {
    asm volatile("{\n\t.reg .pred p;\n\tsetp.ne.u32 p, %5, 0;\n\t"
        "tcgen05.mma.cta_group::1.kind::f16 [%0], [%1], %2, %3, {%4,%4,%4,%4}, p;\n\t}"
        :: "r"(d), "r"(a), "l"(bd), "r"(idesc), "r"(0u), "r"(acc) : "memory");
}
// cg2 SS MMA (M=256 across pair); 8-zero disable-lane vector per example
__device__ __forceinline__ void mma_f16_ss_cg2(u32 d, u64 ad, u64 bd, u32 idesc, u32 acc) {
    asm volatile("{\n\t.reg .pred p;\n\tsetp.ne.u32 p, %6, 0;\n\t"
        "tcgen05.mma.cta_group::2.kind::f16 [%0], %1, %2, %3, "
        "{%4,%4,%4,%4,%4,%4,%4,%4}, p;\n\t}"
        :: "r"(d), "l"(ad), "l"(bd), "r"(idesc), "r"(0u), "r"(0u), "r"(acc)
        : "memory");
}
// SW64 desc (GEMM): layout=4, version=1, SBO=32, LBO=1
#define DESC64_BASE ((4ull<<61)|(1ull<<46)|(32ull<<32)|(1ull<<16))
#define MKDESC64(a) (DESC64_BASE | ((u64)((a) >> 4) & 0x3FFFull))
// SW128 desc (attention): layout=2, version=1, SBO=64, LBO=1
#define DESC128_BASE ((2ull<<61)|(1ull<<46)|(64ull<<32)|(1ull<<16))
#define MKDESC128(a) (DESC128_BASE | ((u64)((a) >> 4) & 0x3FFFull))
#define IDESC_CG2 0x10400490u  // F32 acc, BF16xBF16, M=256 (cg2), N=256
#define IDESC_128 0x8200490u   // M=128, N=128
#define IDESC_64  0x8100490u   // M=128, N=64

#define LDTM32(r, ta) \
    asm volatile("tcgen05.ld.sync.aligned.32x32b.x32.b32 " \
        "{%0,%1,%2,%3,%4,%5,%6,%7,%8,%9,%10,%11,%12,%13,%14,%15," \
        "%16,%17,%18,%19,%20,%21,%22,%23,%24,%25,%26,%27,%28,%29,%30,%31}, [%32];" \
        : "=r"((r)[0]),"=r"((r)[1]),"=r"((r)[2]),"=r"((r)[3]), \
          "=r"((r)[4]),"=r"((r)[5]),"=r"((r)[6]),"=r"((r)[7]), \
          "=r"((r)[8]),"=r"((r)[9]),"=r"((r)[10]),"=r"((r)[11]), \
          "=r"((r)[12]),"=r"((r)[13]),"=r"((r)[14]),"=r"((r)[15]), \
          "=r"((r)[16]),"=r"((r)[17]),"=r"((r)[18]),"=r"((r)[19]), \
          "=r"((r)[20]),"=r"((r)[21]),"=r"((r)[22]),"=r"((r)[23]), \
          "=r"((r)[24]),"=r"((r)[25]),"=r"((r)[26]),"=r"((r)[27]), \
          "=r"((r)[28]),"=r"((r)[29]),"=r"((r)[30]),"=r"((r)[31]) \
        : "r"(ta))

#define STTM8(ta, r) \
    asm volatile("tcgen05.st.sync.aligned.32x32b.x8.b32 [%0], " \
        "{%1,%2,%3,%4,%5,%6,%7,%8};" \
        :: "r"(ta), "r"((r)[0]), "r"((r)[1]), "r"((r)[2]), "r"((r)[3]), \
           "r"((r)[4]), "r"((r)[5]), "r"((r)[6]), "r"((r)[7]) : "memory")
#endif

// ------------------------- embedding ---------------------------------------
__global__ void __launch_bounds__(256) embed_kernel(
        const int* __restrict__ idx, const float* __restrict__ tok,
        const float* __restrict__ pos) {
    int row = blockIdx.x;
    int t = row & (NT - 1);
    int token = idx[row];
    const float4* t4 = (const float4*)(tok + (size_t)token * CD);
    const float4* p4 = (const float4*)(pos + (size_t)t * CD);
    float4 a = t4[threadIdx.x];
    float4 b = p4[threadIdx.x];
    a.x += b.x; a.y += b.y; a.z += b.z; a.w += b.w;
    ((float4*)(g_x + (size_t)row * CD))[threadIdx.x] = a;
}

// ------------------------- split write helper -------------------------------
__device__ __forceinline__ void write_split4(
        __nv_bfloat16* __restrict__ ph, __nv_bfloat16* __restrict__ pl,
        size_t o, float a0, float a1, float a2, float a3) {
    __nv_bfloat16 h0 = __float2bfloat16(a0), h1 = __float2bfloat16(a1);
    __nv_bfloat16 h2 = __float2bfloat16(a2), h3 = __float2bfloat16(a3);
    *(__nv_bfloat162*)&ph[o]     = __nv_bfloat162(h0, h1);
    *(__nv_bfloat162*)&ph[o + 2] = __nv_bfloat162(h2, h3);
    *(__nv_bfloat162*)&pl[o] = __nv_bfloat162(
        __float2bfloat16(a0 - __bfloat162float(h0)),
        __float2bfloat16(a1 - __bfloat162float(h1)));
    *(__nv_bfloat162*)&pl[o + 2] = __nv_bfloat162(
        __float2bfloat16(a2 - __bfloat162float(h2)),
        __float2bfloat16(a3 - __bfloat162float(h3)));
}

// ------------------------- layernorm (fused split) --------------------------
__global__ void __launch_bounds__(256) ln_kernel(
        const float* __restrict__ g, const float* __restrict__ b, int mode) {
    __shared__ float rs[8], rss[8];
    __shared__ float mean_s, rstd_s;
    const float* x = g_x;
    int row = blockIdx.x, tid = threadIdx.x;
    float4 v = ((const float4*)(x + (size_t)row * CD))[tid];
    float s  = v.x + v.y + v.z + v.w;
    float ss = v.x*v.x + v.y*v.y + v.z*v.z + v.w*v.w;
    #pragma unroll
    for (int o = 16; o; o >>= 1) {
        s  += __shfl_xor_sync(0xffffffffu, s,  o);
        ss += __shfl_xor_sync(0xffffffffu, ss, o);
    }
    if ((tid & 31) == 0) { rs[tid >> 5] = s; rss[tid >> 5] = ss; }
    __syncthreads();
    if (tid == 0) {
        float S = 0.f, SS = 0.f;
        #pragma unroll
        for (int i = 0; i < 8; i++) { S += rs[i]; SS += rss[i]; }
        float mean = S * (1.f / CD);
        float var  = SS * (1.f / CD) - mean * mean;
        mean_s = mean;
        rstd_s = rsqrtf(var + 1e-5f);
    }
    __syncthreads();
    float mean = mean_s, rstd = rstd_s;
    float4 gg = ((const float4*)g)[tid];
    float4 bb = ((const float4*)b)[tid];
    float o0 = (v.x - mean) * rstd * gg.x + bb.x;
    float o1 = (v.y - mean) * rstd * gg.y + bb.y;
    float o2 = (v.z - mean) * rstd * gg.z + bb.z;
    float o3 = (v.w - mean) * rstd * gg.w + bb.w;
    if (mode == 1) {
        ((float4*)(g_h + (size_t)row * CD))[tid] = make_float4(o0, o1, o2, o3);
    } else {
        write_split4(g_ah, g_al, (size_t)row * CD + tid * 4, o0, o1, o2, o3);
    }
}

// W[K,N] fp32 -> g_wh/g_wl at element offset woff, [N,K] bf16 (transposed)
__global__ void __launch_bounds__(256) split_w_kernel(
        const float* __restrict__ W, int K, int N, size_t woff) {
    __shared__ float t[32][33];
    int n0 = blockIdx.x * 32, k0 = blockIdx.y * 32;
    int tx = threadIdx.x & 31, ty = threadIdx.x >> 5;
    #pragma unroll
    for (int i = 0; i < 4; i++)
        t[ty + i * 8][tx] = W[(size_t)(k0 + ty + i * 8) * N + n0 + tx];
    __syncthreads();
    #pragma unroll
    for (int i = 0; i < 4; i++) {
        int n = ty + i * 8;
        float a = t[tx][n];
        __nv_bfloat16 hi = __float2bfloat16(a);
        float lo = a - __bfloat162float(hi);
        size_t o = woff + (size_t)(n0 + n) * K + k0 + tx;
        g_wh[o] = hi;
        g_wl[o] = __float2bfloat16(lo);
    }
}

// ----- bf16-split GEMM: cg2 pair computes 256x256 tile, BK=32, 3-stage -----
// Per CTA: 128 M-rows of A, 128 N-cols of B (SW64, cp.async).
#define BM 256
#define BN 256
#define BK 32
#define OFF_AH 0
#define OFF_AL 8192
#define OFF_BH 16384
#define OFF_BL 24576
#define STAGE  32768
#define NSTG   3
#define GEMM_SMEM (NSTG*STAGE + 2048)

__device__ __forceinline__ void load_stage_cg2(
        u32 stg, const __nv_bfloat16* __restrict__ ah,
        const __nv_bfloat16* __restrict__ al,
        const __nv_bfloat16* __restrict__ bh,
        const __nv_bfloat16* __restrict__ bl,
        int mrow0, int ncol0, int k0, int K, int tid) {
    int cc = tid & 3;
    int r0 = tid >> 2;
    #pragma unroll
    for (int j = 0; j < 2; j++) {
        int r = r0 + j * 64;
        u32 so = SWZ64((u32)(r * 64 + cc * 16));
        size_t aoff = (size_t)(mrow0 + r) * K + k0 + cc * 8;
        size_t boff = (size_t)(ncol0 + r) * K + k0 + cc * 8;
        CP_ASYNC16(stg + OFF_AH + so, (const void*)(ah + aoff));
        CP_ASYNC16(stg + OFF_AL + so, (const void*)(al + aoff));
        CP_ASYNC16(stg + OFF_BH + so, (const void*)(bh + boff));
        CP_ASYNC16(stg + OFF_BL + so, (const void*)(bl + boff));
    }
}

// EP=0: fp32 out. EP=1: +bias +res, fp32 out.
// EP=2: +bias, relu, split out to g_bh/g_bl. EP=3: QKV demux to g_q/g_k/g_v.
template<int EP>
__device__ __forceinline__ void ep_write4(
        float c0, float c1, float c2, float c3,
        const float* __restrict__ bias, const float* __restrict__ res,
        float* __restrict__ out, size_t m, int n, int N) {
    if (EP == 1 || EP == 2) {
        float4 bv = *(const float4*)&bias[n];
        c0 += bv.x; c1 += bv.y; c2 += bv.z; c3 += bv.w;
    }
    if (EP == 1) {
        float4 rv = *(const float4*)&res[m * N + n];
        c0 += rv.x; c1 += rv.y; c2 += rv.z; c3 += rv.w;
        *(float4*)&out[m * N + n] = make_float4(c0, c1, c2, c3);
    } else if (EP == 2) {
        c0 = fmaxf(c0, 0.f); c1 = fmaxf(c1, 0.f);
        c2 = fmaxf(c2, 0.f); c3 = fmaxf(c3, 0.f);
        write_split4(g_bh, g_bl, m * N + n, c0, c1, c2, c3);
    } else if (EP == 3) {
        int which = n >> 10;
        float* o = (which == 0) ? g_q : (which == 1) ? g_k : g_v;
        *(float4*)&o[m * CD + (n & 1023)] = make_float4(c0, c1, c2, c3);
    } else {
        *(float4*)&out[m * N + n] = make_float4(c0, c1, c2, c3);
    }
}

template<int EP>
__global__ void __launch_bounds__(256, 1) __cluster_dims__(2, 1, 1)
tcgemm_kernel(const float* __restrict__ bias, int asel, int rsel, int osel,
              int N, int K, size_t woff) {
    extern __shared__ char dsm[];
    u32 sb = (smem_u32(dsm) + 1023u) & ~1023u;
    int tid = threadIdx.x, wid = tid >> 5, lid = tid & 31;
    int rank = blockIdx.x & 1;             // cluster ctarank (cluster.x == 2)
    int n0 = (blockIdx.x >> 1) * BN;
    int m0 = blockIdx.y * BM;
    int mrow0 = m0 + rank * 128;           // this CTA's A rows
    int ncol0 = n0 + rank * 128;           // this CTA's B cols
    const int NS = K / BK;
    const float* res = buf(rsel);
    float* out = buf(osel);
    const __nv_bfloat16* Ah = asel ? g_bh : g_ah;
    const __nv_bfloat16* Al = asel ? g_bl : g_al;
    const __nv_bfloat16* Bh = g_wh + woff;
    const __nv_bfloat16* Bl = g_wl + woff;

#if HAS_TCGEN05
    const u32 TM_PTR = sb + NSTG * STAGE;
    u32 mb[3] = {TM_PTR + 8, TM_PTR + 16, TM_PTR + 24};   // MMA-done (multicast)

    if (wid == 0) {
        asm volatile("tcgen05.alloc.cta_group::2.sync.aligned.shared::cta.b32 [%0], %1;"
                     :: "r"(TM_PTR), "r"(256u) : "memory");
        asm volatile("tcgen05.relinquish_alloc_permit.cta_group::2.sync.aligned;");
    }
    if (tid == 0) {
        mbar_init(mb[0], 1); mbar_init(mb[1], 1); mbar_init(mb[2], 1);
    }
    __syncthreads();
    u32 tmem;
    asm("ld.shared.b32 %0, [%1];" : "=r"(tmem) : "r"(TM_PTR));

    load_stage_cg2(sb, Ah, Al, Bh, Bl, mrow0, ncol0, 0, K, tid);
    CP_COMMIT();
    load_stage_cg2(sb + STAGE, Ah, Al, Bh, Bl, mrow0, ncol0, BK, K, tid);
    CP_COMMIT();

    // mbarriers initialized in both CTAs before any multicast commit
    CLUSTER_SYNC();

    u32 phx[3] = {0, 0, 0};
    for (int s = 0; s < NS; s++) {
        int b = s - (s / 3) * 3;
        u32 stg = sb + b * STAGE;
        if (s + 1 < NS) CP_WAIT1();
        else            CP_WAIT0();
        // both CTAs' stage-s tiles resident before leader's cg2 MMA reads them
        CLUSTER_SYNC();
        if (rank == 0 && wid == 0) {
            asm volatile("fence.proxy.async.shared::cta;" ::: "memory");
            if (elect1()) {
                u64 dah = MKDESC64(stg + OFF_AH);
                u64 dal = MKDESC64(stg + OFF_AL);
                u64 dbh = MKDESC64(stg + OFF_BH);
                u64 dbl = MKDESC64(stg + OFF_BL);
                #pragma unroll
                for (int kk = 0; kk < 2; kk++) {
                    mma_f16_ss_cg2(tmem, dah + kk * 2, dbh + kk * 2, IDESC_CG2,
                                   (s == 0 && kk == 0) ? 0u : 1u);
                    mma_f16_ss_cg2(tmem, dah + kk * 2, dbl + kk * 2, IDESC_CG2, 1u);
                    mma_f16_ss_cg2(tmem, dal + kk * 2, dbh + kk * 2, IDESC_CG2, 1u);
                }
                asm volatile(
                    "tcgen05.commit.cta_group::2.mbarrier::arrive::one.shared::cluster.multicast::cluster.b64 [%0], %1;"
                    :: "r"(mb[b]), "h"((unsigned short)3) : "memory");
            }
        }
        if (s + 2 < NS) {
            int nb = (s + 2) - ((s + 2) / 3) * 3;
            if (s >= 1) { mbar_wait(mb[nb], phx[nb]); phx[nb] ^= 1u; }
            load_stage_cg2(sb + nb * STAGE, Ah, Al, Bh, Bl, mrow0, ncol0,
                           (s + 2) * BK, K, tid);
            CP_COMMIT();
        }
    }
    {
        int fb = (NS - 1) - ((NS - 1) / 3) * 3;
        mbar_wait(mb[fb], phx[fb]);
    }
    asm volatile("tcgen05.fence::after_thread_sync;" ::: "memory");

    {
        // each CTA drains its own 128x256 D slice; 8 warps: 4 lanesets x 2 col halves
        int colblk = (wid >> 2) * 128;
        size_t m = (size_t)mrow0 + (wid & 3) * 32 + lid;
        u32 tbase = tmem + colblk;
        for (int c0 = 0; c0 < 128; c0 += 32) {
            u32 r[32];
            LDTM32(r, tbase + c0);
            asm volatile("tcgen05.wait::ld.sync.aligned;" ::: "memory");
            #pragma unroll
            for (int q = 0; q < 8; q++) {
                int n = n0 + colblk + c0 + q * 4;
                ep_write4<EP>(__uint_as_float(r[q*4+0]), __uint_as_float(r[q*4+1]),
                              __uint_as_float(r[q*4+2]), __uint_as_float(r[q*4+3]),
                              bias, res, out, m, n, N);
            }
        }
    }
    __syncthreads();
    if (wid == 0) {
        asm volatile("tcgen05.dealloc.cta_group::2.sync.aligned.b32 %0, %1;"
                     :: "r"(tmem), "r"(256u));
    }
    // no CTA may exit while the pair's TMEM/SMEM interactions are in flight
    CLUSTER_SYNC();
#else
    // Base-PTX fallback: never selected at runtime (sm_103a cubin exists).
    (void)sb; (void)lid; (void)wid;
    int r = tid >> 1, half = tid & 1;
    size_t m = (size_t)mrow0 + r;
    for (int jn4 = half * 64; jn4 < half * 64 + 64; jn4 += 4) {
        float c[4];
        #pragma unroll
        for (int jj = 0; jj < 4; jj++) {
            int n = n0 + rank * 128 + jn4 + jj;
            float acc = 0.f;
            const __nv_bfloat16* ah = Ah + m * K;
            const __nv_bfloat16* al = Al + m * K;
            const __nv_bfloat16* bh = Bh + (size_t)n * K;
            const __nv_bfloat16* bl = Bl + (size_t)n * K;
            for (int k = 0; k < K; k++) {
                float av = __bfloat162float(ah[k]) + __bfloat162float(al[k]);
                float bv = __bfloat162float(bh[k]) + __bfloat162float(bl[k]);
                acc += av * bv;
            }
            c[jj] = acc;
        }
        ep_write4<EP>(c[0], c[1], c[2], c[3], bias, res, out,
                      m, n0 + rank * 128 + jn4, N);
    }
    // also cover the other 128 rows x other col half to keep full coverage
    size_t m2 = (size_t)mrow0 + r;
    (void)m2;
    // full-tile coverage: second pass over remaining columns
    for (int jn4 = (1 - half) * 64; jn4 < (1 - half) * 64 + 64; jn4 += 4) {
        float c[4];
        #pragma unroll
        for (int jj = 0; jj < 4; jj++) {
            int n = n0 + (1 - rank) * 128 + jn4 + jj;
            float acc = 0.f;
            const __nv_bfloat16* ah = Ah + m * K;
            const __nv_bfloat16* al = Al + m * K;
            const __nv_bfloat16* bh = Bh + (size_t)n * K;
            const __nv_bfloat16* bl = Bl + (size_t)n * K;
            for (int k = 0; k < K; k++) {
                float av = __bfloat162float(ah[k]) + __bfloat162float(al[k]);
                float bv = __bfloat162float(bh[k]) + __bfloat162float(bl[k]);
                acc += av * bv;
            }
            c[jj] = acc;
        }
        ep_write4<EP>(c[0], c[1], c[2], c[3], bias, res, out,
                      m, n0 + (1 - rank) * 128 + jn4, N);
    }
#endif
}

// ------------------------- tensor-core flash attention ----------------------
#define ATT_QH 0
#define ATT_QL 16384
#define ATT_KH 32768
#define ATT_KL 49152
#define ATT_VH 65536
#define ATT_VL 81920
#define ATT_CTRL 98304
#define ATT_SMEM (98304 + 64)

#if HAS_TCGEN05
// load a 128x64 fp32 tile (row stride CD) -> split bf16 smem, SW128 rows of 128B
__device__ __forceinline__ void att_load_split(
        u32 dh, u32 dl, const float* __restrict__ g, int tid) {
    int cc = tid & 3, r0 = tid >> 2;
    #pragma unroll
    for (int j = 0; j < 4; j++) {
        int r = r0 + j * 32;
        const float* src = g + (size_t)r * CD + cc * 16;
        float f[16];
        #pragma unroll
        for (int i = 0; i < 4; i++) {
            float4 t = *(const float4*)(src + i * 4);
            f[i*4] = t.x; f[i*4+1] = t.y; f[i*4+2] = t.z; f[i*4+3] = t.w;
        }
        u32 hw[8], lw[8];
        #pragma unroll
        for (int i = 0; i < 8; i++) {
            float a = f[2*i], b = f[2*i+1];
            __nv_bfloat16 h0 = __float2bfloat16(a), h1 = __float2bfloat16(b);
            hw[i] = packbf2(a, b);
            lw[i] = packbf2(a - __bfloat162float(h0), b - __bfloat162float(h1));
        }
        u32 bo = (u32)(r * 128 + cc * 32);
        sts128(dh + SWZ128(bo),      make_uint4(hw[0], hw[1], hw[2], hw[3]));
        sts128(dh + SWZ128(bo + 16), make_uint4(hw[4], hw[5], hw[6], hw[7]));
        sts128(dl + SWZ128(bo),      make_uint4(lw[0], lw[1], lw[2], lw[3]));
        sts128(dl + SWZ128(bo + 16), make_uint4(lw[4], lw[5], lw[6], lw[7]));
    }
}

// load V 128x64 fp32 -> transposed split smem vt[d][key], blocked atoms:
// block0 keys 0-63 at 0, block1 keys 64-127 at 8192. rows = d (128B each).
__device__ __forceinline__ void att_load_split_vt(
        u32 dh, u32 dl, const float* __restrict__ g, int tid) {
    int cc = tid & 3, r0 = tid >> 2;
    #pragma unroll
    for (int j = 0; j < 4; j++) {
        int r = r0 + j * 32;              // key index
        const float* src = g + (size_t)r * CD + cc * 16;
        float f[16];
        #pragma unroll
        for (int i = 0; i < 4; i++) {
            float4 t = *(const float4*)(src + i * 4);
            f[i*4] = t.x; f[i*4+1] = t.y; f[i*4+2] = t.z; f[i*4+3] = t.w;
        }
        u32 blk = (r >= 64) ? 8192u : 0u;
        u32 rr = (u32)(r & 63) * 2;
        #pragma unroll
        for (int i = 0; i < 16; i++) {
            int d = cc * 16 + i;
            __nv_bfloat16 hv = __float2bfloat16(f[i]);
            __nv_bfloat16 lv = __float2bfloat16(f[i] - __bfloat162float(hv));
            u32 off = blk + (u32)d * 128 + rr;
            STS16(dh + SWZ128(off), __bfloat16_as_ushort(hv));
            STS16(dl + SWZ128(off), __bfloat16_as_ushort(lv));
        }
    }
}
#endif

__global__ void __launch_bounds__(128, 2) attn_kernel() {
#if HAS_TCGEN05
    extern __shared__ char dsm[];
    u32 sb = (smem_u32(dsm) + 1023u) & ~1023u;
    const u32 TM_PTR = sb + ATT_CTRL;
    const u32 MB_S = TM_PTR + 8, MB_PV = TM_PTR + 16;

    int tid = threadIdx.x, wid = tid >> 5;
    int bh = blockIdx.x, b = bh >> 4, h = bh & 15;
    int qb = blockIdx.y;
    const size_t base = (size_t)b * NT * CD + h * HSD;
    const u32 woff = (u32)(wid << 21);

    if (wid == 0) {
        asm volatile("tcgen05.alloc.cta_group::1.sync.aligned.shared::cta.b32 [%0], %1;"
                     :: "r"(TM_PTR), "r"(256u) : "memory");
        asm volatile("tcgen05.relinquish_alloc_permit.cta_group::1.sync.aligned;");
    }
    if (tid == 0) { mbar_init(MB_S, 1); mbar_init(MB_PV, 1); }
    __syncthreads();
    u32 tmem;
    asm("ld.shared.b32 %0, [%1];" : "=r"(tmem) : "r"(TM_PTR));

    att_load_split(sb + ATT_QH, sb + ATT_QL,
                   g_q + base + (size_t)(qb * 128) * CD, tid);

    float m_i = -1e30f, l_i = 0.f;
    float o[64];
    #pragma unroll
    for (int d = 0; d < 64; d++) o[d] = 0.f;
    const float scale = 0.125f;
    u32 ph_s = 0, ph_pv = 0;

    for (int kb = 0; kb <= qb; kb++) {
        __syncthreads();
        att_load_split(sb + ATT_KH, sb + ATT_KL,
                       g_k + base + (size_t)(kb * 128) * CD, tid);
        att_load_split_vt(sb + ATT_VH, sb + ATT_VL,
                          g_v + base + (size_t)(kb * 128) * CD, tid);
        asm volatile("fence.proxy.async.shared::cta;" ::: "memory");
        __syncthreads();

        if (wid == 0 && elect1()) {
            u64 dqh = MKDESC128(sb + ATT_QH), dql = MKDESC128(sb + ATT_QL);
            u64 dkh = MKDESC128(sb + ATT_KH), dkl = MKDESC128(sb + ATT_KL);
            #pragma unroll
            for (int ks = 0; ks < 4; ks++) {
                mma_f16_ss(tmem, dqh + ks*2, dkh + ks*2, IDESC_128, ks == 0 ? 0u : 1u);
                mma_f16_ss(tmem, dqh + ks*2, dkl + ks*2, IDESC_128, 1u);
                mma_f16_ss(tmem, dql + ks*2, dkh + ks*2, IDESC_128, 1u);
            }
            asm volatile(
                "tcgen05.commit.cta_group::1.mbarrier::arrive::one.shared::cluster.b64 [%0];"
                :: "r"(MB_S) : "memory");
        }
        mbar_wait(MB_S, ph_s); ph_s ^= 1u;
        asm volatile("tcgen05.fence::after_thread_sync;" ::: "memory");

        u32 sr[128];
        LDTM32(sr +  0, tmem +  0);
        LDTM32(sr + 32, tmem + 32);
        LDTM32(sr + 64, tmem + 64);
        LDTM32(sr + 96, tmem + 96);
        asm volatile("tcgen05.wait::ld.sync.aligned;" ::: "memory");

        float tm = -1e30f;
        if (kb == qb) {
            #pragma unroll
            for (int j = 0; j < 128; j++) {
                float v = (j > tid) ? -1e30f : __uint_as_float(sr[j]) * scale;
                sr[j] = __float_as_uint(v);
                tm = fmaxf(tm, v);
            }
        } else {
            #pragma unroll
            for (int j = 0; j < 128; j++) {
                float v = __uint_as_float(sr[j]) * scale;
                sr[j] = __float_as_uint(v);
                tm = fmaxf(tm, v);
            }
        }
        float nm = fmaxf(m_i, tm);
        float corr = __expf(m_i - nm);

        float lsum = 0.f;
        #pragma unroll
        for (int c = 0; c < 8; c++) {
            u32 hw[8], lw[8];
            #pragma unroll
            for (int i = 0; i < 8; i++) {
                int j = c * 16 + i * 2;
                float e0 = __expf(__uint_as_float(sr[j])     - nm);
                float e1 = __expf(__uint_as_float(sr[j + 1]) - nm);
                lsum += e0 + e1;
                __nv_bfloat16 h0 = __float2bfloat16(e0), h1 = __float2bfloat16(e1);
                hw[i] = packbf2(e0, e1);
                lw[i] = packbf2(e0 - __bfloat162float(h0), e1 - __bfloat162float(h1));
            }
            STTM8(tmem + 128 + c * 8 + woff, hw);
            STTM8(tmem + 192 + c * 8 + woff, lw);
        }
        asm volatile("tcgen05.wait::st.sync.aligned;" ::: "memory");
        l_i = l_i * corr + lsum;
        m_i = nm;
        asm volatile("tcgen05.fence::before_thread_sync;" ::: "memory");
        __syncthreads();

        if (wid == 0 && elect1()) {
            asm volatile("tcgen05.fence::after_thread_sync;" ::: "memory");
            u64 dvh = MKDESC128(sb + ATT_VH), dvl = MKDESC128(sb + ATT_VL);
            #pragma unroll
            for (int ks = 0; ks < 8; ks++) {
                u64 off = (ks < 4) ? (u64)(ks * 2) : (u64)(512 + (ks - 4) * 2);
                u32 aph = tmem + 128 + ks * 8;
                u32 apl = tmem + 192 + ks * 8;
                mma_f16_ts(tmem, aph, dvh + off, IDESC_64, ks == 0 ? 0u : 1u);
                mma_f16_ts(tmem, aph, dvl + off, IDESC_64, 1u);
                mma_f16_ts(tmem, apl, dvh + off, IDESC_64, 1u);
            }
            asm volatile(
                "tcgen05.commit.cta_group::1.mbarrier::arrive::one.shared::cluster.b64 [%0];"
                :: "r"(MB_PV) : "memory");
        }
        mbar_wait(MB_PV, ph_pv); ph_pv ^= 1u;
        asm volatile("tcgen05.fence::after_thread_sync;" ::: "memory");

        u32 org[64];
        LDTM32(org,      tmem +  0);
        LDTM32(org + 32, tmem + 32);
        asm volatile("tcgen05.wait::ld.sync.aligned;" ::: "memory");
        #pragma unroll
        for (int d = 0; d < 64; d++)
            o[d] = o[d] * corr + __uint_as_float(org[d]);
    }

    {
        float inv = 1.f / l_i;
        size_t obase = ((size_t)(b * NT + qb * 128 + tid)) * CD + h * HSD;
        #pragma unroll
        for (int g4 = 0; g4 < 16; g4++) {
            write_split4(g_ah, g_al, obase + g4 * 4,
                         o[g4*4+0] * inv, o[g4*4+1] * inv,
                         o[g4*4+2] * inv, o[g4*4+3] * inv);
        }
    }
    __syncthreads();
    if (wid == 0) {
        asm volatile("tcgen05.dealloc.cta_group::1.sync.aligned.b32 %0, %1;"
                     :: "r"(tmem), "r"(256u));
    }
#else
    int tid = threadIdx.x;
    int bh = blockIdx.x, b = bh >> 4, h = bh & 15;
    int t = blockIdx.y * 128 + tid;
    const size_t base = (size_t)b * NT * CD + h * HSD;
    const float* q = &g_q[base + (size_t)t * CD];
    float m = -1e30f, l = 0.f, o[64];
    for (int d = 0; d < 64; d++) o[d] = 0.f;
    for (int key = 0; key <= t; key++) {
        const float* kk = &g_k[base + (size_t)key * CD];
        float s = 0.f;
        for (int d = 0; d < 64; d++) s += q[d] * kk[d];
        s *= 0.125f;
        float nm = fmaxf(m, s);
        float corr = __expf(m - nm), e = __expf(s - nm);
        l = l * corr + e; m = nm;
        const float* vv = &g_v[base + (size_t)key * CD];
        for (int d = 0; d < 64; d++) o[d] = o[d] * corr + e * vv[d];
    }
    float inv = 1.f / l;
    size_t obase = ((size_t)(b * NT + t)) * CD + h * HSD;
    for (int g4 = 0; g4 < 16; g4++)
        write_split4(g_ah, g_al, obase + g4 * 4,
                     o[g4*4+0]*inv, o[g4*4+1]*inv, o[g4*4+2]*inv, o[g4*4+3]*inv);
#endif
}

// ------------------------- LM head (N=67) ----------------------------------
__global__ void __launch_bounds__(128) lm_kernel(
        const float* __restrict__ W, const float* __restrict__ bias,
        float* __restrict__ out) {
    __shared__ float hs[CD];
    const float* h = g_h;
    int row = blockIdx.x;
    int tid = threadIdx.x;
    ((float4*)hs)[tid]       = ((const float4*)(h + (size_t)row * CD))[tid];
    ((float4*)hs)[tid + 128] = ((const float4*)(h + (size_t)row * CD))[tid + 128];
    __syncthreads();
    if (tid < NV) {
        float a0 = 0.f, a1 = 0.f, a2 = 0.f, a3 = 0.f;
        #pragma unroll 4
        for (int kk = 0; kk < CD; kk += 4) {
            a0 += hs[kk + 0] * W[(kk + 0) * NV + tid];
            a1 += hs[kk + 1] * W[(kk + 1) * NV + tid];
            a2 += hs[kk + 2] * W[(kk + 2) * NV + tid];
            a3 += hs[kk + 3] * W[(kk + 3) * NV + tid];
        }
        out[(size_t)row * NV + tid] = bias[tid] + ((a0 + a1) + (a2 + a3));
    }
}

// ------------------------- launch ------------------------------------------
static void split_layer(int l, cudaStream_t st,
                        const float* Wq, const float* Wk, const float* Wv,
                        const float* Wo, const float* W1, const float* W2) {
    dim3 wC(CD / 32, CD / 32);
    dim3 w1g(FFD / 32, CD / 32);
    dim3 w2g(CD / 32, FFD / 32);
    size_t p = (size_t)(l & 1) * WSEG;
    split_w_kernel<<<wC, 256, 0, st>>>(Wq + (size_t)l * CD * CD, CD, CD, p + WOFF_QKV);
    split_w_kernel<<<wC, 256, 0, st>>>(Wk + (size_t)l * CD * CD, CD, CD, p + WOFF_QKV + 1024 * 1024);
    split_w_kernel<<<wC, 256, 0, st>>>(Wv + (size_t)l * CD * CD, CD, CD, p + WOFF_QKV + 2 * 1024 * 1024);
    split_w_kernel<<<wC, 256, 0, st>>>(Wo + (size_t)l * CD * CD, CD, CD, p + WOFF_WO);
    split_w_kernel<<<w1g, 256, 0, st>>>(W1 + (size_t)l * CD * FFD, CD, FFD, p + WOFF_W1);
    split_w_kernel<<<w2g, 256, 0, st>>>(W2 + (size_t)l * FFD * CD, FFD, CD, p + WOFF_W2);
}

extern "C" void kernel_launch(void* const* d_in, const int* in_sizes, int n_in,
                              void* d_out, int out_size) {
    const int*   idx  = (const int*)  d_in[0];
    const float* tok  = (const float*)d_in[1];
    const float* pos  = (const float*)d_in[2];
    const float* Wq   = (const float*)d_in[3];
    const float* Wk   = (const float*)d_in[4];
    const float* Wv   = (const float*)d_in[5];
    const float* Wo   = (const float*)d_in[6];
    const float* bo   = (const float*)d_in[7];
    const float* ln1g = (const float*)d_in[8];
    const float* ln1b = (const float*)d_in[9];
    const float* ln2g = (const float*)d_in[10];
    const float* ln2b = (const float*)d_in[11];
    const float* W1   = (const float*)d_in[12];
    const float* b1   = (const float*)d_in[13];
    const float* W2   = (const float*)d_in[14];
    const float* b2   = (const float*)d_in[15];
    const float* lnfg = (const float*)d_in[16];
    const float* lnfb = (const float*)d_in[17];
    const float* Wlm  = (const float*)d_in[18];
    const float* blm  = (const float*)d_in[19];
    float* out = (float*)d_out;

    // side stream + events (host-side objects, created once; no device memory)
    static cudaStream_t s2 = nullptr;
    static cudaEvent_t evA[NL], evB[NL];
    if (!s2) {
        cudaStreamCreateWithFlags(&s2, cudaStreamNonBlocking);
        for (int i = 0; i < NL; i++) {
            cudaEventCreateWithFlags(&evA[i], cudaEventDisableTiming);
            cudaEventCreateWithFlags(&evB[i], cudaEventDisableTiming);
        }
    }

    cudaFuncSetAttribute(tcgemm_kernel<0>,
                         cudaFuncAttributeMaxDynamicSharedMemorySize, GEMM_SMEM);
    cudaFuncSetAttribute(tcgemm_kernel<1>,
                         cudaFuncAttributeMaxDynamicSharedMemorySize, GEMM_SMEM);
    cudaFuncSetAttribute(tcgemm_kernel<2>,
                         cudaFuncAttributeMaxDynamicSharedMemorySize, GEMM_SMEM);
    cudaFuncSetAttribute(tcgemm_kernel<3>,
                         cudaFuncAttributeMaxDynamicSharedMemorySize, GEMM_SMEM);
    cudaFuncSetAttribute(attn_kernel,
                         cudaFuncAttributeMaxDynamicSharedMemorySize, ATT_SMEM);

    // grids: x = n-tiles * 2 (cluster pairs), y = m-tiles
    dim3 gC(2 * CD / BN, NM / BM);        // (8, 32)
    dim3 gQKV(2 * 3 * CD / BN, NM / BM);  // (24, 32)
    dim3 gF(2 * FFD / BN, NM / BM);       // (32, 32)
    dim3 gA(NB * NH, NT / 128);           // (128, 8)

    embed_kernel<<<NM, 256>>>(idx, tok, pos);
    split_layer(0, 0, Wq, Wk, Wv, Wo, W1, W2);   // layer 0 weights: exposed

    for (int l = 0; l < NL; l++) {
        size_t p = (size_t)(l & 1) * WSEG;

        // fork: prefetch layer l+1's weights on side stream into other segment
        if (l + 1 < NL) {
            cudaEventRecord(evA[l], 0);
            cudaStreamWaitEvent(s2, evA[l], 0);
            split_layer(l + 1, s2, Wq, Wk, Wv, Wo, W1, W2);
            cudaEventRecord(evB[l], s2);
        }

        ln_kernel<<<NM, 256>>>(ln1g + (size_t)l * CD, ln1b + (size_t)l * CD, 0);
        tcgemm_kernel<3><<<gQKV, 256, GEMM_SMEM>>>(
            nullptr, 0, 0, 0, 3 * CD, CD, p + WOFF_QKV);
        attn_kernel<<<gA, 128, ATT_SMEM>>>();
        tcgemm_kernel<1><<<gC, 256, GEMM_SMEM>>>(
            bo + (size_t)l * CD, 0, 0, 0, CD, CD, p + WOFF_WO);
        ln_kernel<<<NM, 256>>>(ln2g + (size_t)l * CD, ln2b + (size_t)l * CD, 0);
        tcgemm_kernel<2><<<gF, 256, GEMM_SMEM>>>(
            b1 + (size_t)l * FFD, 0, 0, 0, FFD, CD, p + WOFF_W1);
        tcgemm_kernel<1><<<gC, 256, GEMM_SMEM>>>(
            b2 + (size_t)l * CD, 1, 0, 0, CD, FFD, p + WOFF_W2);

        // join: next layer's QKV GEMM needs the prefetched weights
        if (l + 1 < NL) cudaStreamWaitEvent(0, evB[l], 0);
    }
    ln_kernel<<<NM, 256>>>(lnfg, lnfb, 1);
    lm_kernel<<<NM, 128>>>(Wlm, blm, out);
}

// round 15
// speedup vs baseline: 1.3701x; 1.3701x over previous
#include <cuda_runtime.h>
#include <cuda_bf16.h>
#include <cstdint>
#include <cstddef>

#define NL 6
#define NH 16
#define CD 1024
#define HSD 64
#define FFD 4096
#define NV 67
#define NB 8
#define NT 1024
#define NM (NB*NT)   // 8192 rows

typedef unsigned long long u64;
typedef unsigned int u32;

// Arch-specific feature gate: tcgen05 only exists in the sm_103a cubin pass.
#if defined(__CUDA_ARCH__) && (defined(__CUDA_ARCH_FEAT_SM103_ALL) || defined(__CUDA_ARCH_SPECIFIC__))
#define HAS_TCGEN05 1
#else
#define HAS_TCGEN05 0
#endif

// weight segment layout (elements): QKV@0 (3M), Wo@3M (1M), W1@4M (4M), W2@8M (4M)
#define WSEG  12582912ull            // 12M elements per layer-parity segment
#define WOFF_QKV 0ull
#define WOFF_WO  3145728ull
#define WOFF_W1  4194304ull
#define WOFF_W2  8388608ull

// ------------------------- scratch (device globals, no allocation) ---------
__device__ float g_x [(size_t)NM*CD];
__device__ float g_h [(size_t)NM*CD];
__device__ float g_q [(size_t)NM*CD];
__device__ float g_k [(size_t)NM*CD];
__device__ float g_v [(size_t)NM*CD];
// bf16 split buffers: two activation pairs (ping/pong) + double-buffered weights
__device__ __nv_bfloat16 g_ah[(size_t)NM*FFD];
__device__ __nv_bfloat16 g_al[(size_t)NM*FFD];
__device__ __nv_bfloat16 g_bh[(size_t)NM*FFD];
__device__ __nv_bfloat16 g_bl[(size_t)NM*FFD];
__device__ __nv_bfloat16 g_wh[2*WSEG];
__device__ __nv_bfloat16 g_wl[2*WSEG];

__device__ __forceinline__ float* buf(int which) {
    switch (which) {
        case 0: return g_x;
        case 1: return g_h;
        case 2: return g_q;
        case 3: return g_k;
        default: return g_v;
    }
}

// ------------------------- PTX helpers -------------------------------------
__device__ __forceinline__ u32 smem_u32(const void* p) {
    u32 a;
    asm("{ .reg .u64 t; cvta.to.shared.u64 t, %1; cvt.u32.u64 %0, t; }"
        : "=r"(a) : "l"(p));
    return a;
}
#define SWZ64(o)  ((o) ^ (((o) >> 3) & 0x30))
#define SWZ128(o) ((o) ^ (((o) >> 3) & 0x70))

#define CP_ASYNC16(dst, src) \
    asm volatile("cp.async.cg.shared.global [%0], [%1], 16;" \
                 :: "r"(dst), "l"(src) : "memory")
#define CP_COMMIT() asm volatile("cp.async.commit_group;" ::: "memory")
#define CP_WAIT0()  asm volatile("cp.async.wait_group 0;" ::: "memory")
#define CP_WAIT1()  asm volatile("cp.async.wait_group 1;" ::: "memory")

#define STS16(addr, v) \
    asm volatile("st.shared.u16 [%0], %1;" :: "r"(addr), "h"(v) : "memory")

__device__ __forceinline__ void sts128(u32 addr, uint4 v) {
    asm volatile("st.shared.v4.b32 [%0], {%1,%2,%3,%4};"
                 :: "r"(addr), "r"(v.x), "r"(v.y), "r"(v.z), "r"(v.w) : "memory");
}

__device__ __forceinline__ u32 packbf2(float a, float b) {
    __nv_bfloat162 t(__float2bfloat16(a), __float2bfloat16(b));
    return *(u32*)&t;
}

__device__ __forceinline__ void mbar_init(u32 addr, u32 cnt) {
    asm volatile("mbarrier.init.shared.b64 [%0], %1;" :: "r"(addr), "r"(cnt) : "memory");
}
__device__ __forceinline__ void mbar_wait(u32 addr, u32 phase) {
    asm volatile("{\n\t.reg .pred P;\n\t"
        "W_%=:\n\t"
        "mbarrier.try_wait.parity.acquire.cta.shared::cta.b64 P, [%0], %1, 0x989680;\n\t"
        "@P bra.uni D_%=;\n\t"
        "bra.uni W_%=;\n\t"
        "D_%=:\n\t}"
        :: "r"(addr), "r"(phase) : "memory");
}

#if HAS_TCGEN05
__device__ __forceinline__ u32 elect1() {
    u32 pred;
    asm volatile("{\n\t.reg .pred p;\n\telect.sync _|p, 0xFFFFFFFF;\n\t"
                 "selp.b32 %0, 1, 0, p;\n\t}" : "=r"(pred));
    return pred;
}
__device__ __forceinline__ void mma_f16_ss(u32 d, u64 ad, u64 bd, u32 idesc, u32 acc) {
    asm volatile("{\n\t.reg .pred p;\n\tsetp.ne.u32 p, %5, 0;\n\t"
        "tcgen05.mma.cta_group::1.kind::f16 [%0], %1, %2, %3, {%4,%4,%4,%4}, p;\n\t}"
        :: "r"(d), "l"(ad), "l"(bd), "r"(idesc), "r"(0u), "r"(acc) : "memory");
}
__device__ __forceinline__ void mma_f16_ts(u32 d, u32 a, u64 bd, u32 idesc, u32 acc) {
    asm volatile("{\n\t.reg .pred p;\n\tsetp.ne.u32 p, %5, 0;\n\t"
        "tcgen05.mma.cta_group::1.kind::f16 [%0], [%1], %2, %3, {%4,%4,%4,%4}, p;\n\t}"
        :: "r"(d), "r"(a), "l"(bd), "r"(idesc), "r"(0u), "r"(acc) : "memory");
}
// SW64 desc (GEMM): layout=4, version=1, SBO=32, LBO=1
#define DESC64_BASE ((4ull<<61)|(1ull<<46)|(32ull<<32)|(1ull<<16))
#define MKDESC64(a) (DESC64_BASE | ((u64)((a) >> 4) & 0x3FFFull))
// SW128 desc (attention): layout=2, version=1, SBO=64, LBO=1
#define DESC128_BASE ((2ull<<61)|(1ull<<46)|(64ull<<32)|(1ull<<16))
#define MKDESC128(a) (DESC128_BASE | ((u64)((a) >> 4) & 0x3FFFull))
#define IDESC_256 0x8400490u   // F32 acc, BF16xBF16, M=128, N=256
#define IDESC_128 0x8200490u   // M=128, N=128
#define IDESC_64  0x8100490u   // M=128, N=64

#define LDTM32(r, ta) \
    asm volatile("tcgen05.ld.sync.aligned.32x32b.x32.b32 " \
        "{%0,%1,%2,%3,%4,%5,%6,%7,%8,%9,%10,%11,%12,%13,%14,%15," \
        "%16,%17,%18,%19,%20,%21,%22,%23,%24,%25,%26,%27,%28,%29,%30,%31}, [%32];" \
        : "=r"((r)[0]),"=r"((r)[1]),"=r"((r)[2]),"=r"((r)[3]), \
          "=r"((r)[4]),"=r"((r)[5]),"=r"((r)[6]),"=r"((r)[7]), \
          "=r"((r)[8]),"=r"((r)[9]),"=r"((r)[10]),"=r"((r)[11]), \
          "=r"((r)[12]),"=r"((r)[13]),"=r"((r)[14]),"=r"((r)[15]), \
          "=r"((r)[16]),"=r"((r)[17]),"=r"((r)[18]),"=r"((r)[19]), \
          "=r"((r)[20]),"=r"((r)[21]),"=r"((r)[22]),"=r"((r)[23]), \
          "=r"((r)[24]),"=r"((r)[25]),"=r"((r)[26]),"=r"((r)[27]), \
          "=r"((r)[28]),"=r"((r)[29]),"=r"((r)[30]),"=r"((r)[31]) \
        : "r"(ta))

#define STTM8(ta, r) \
    asm volatile("tcgen05.st.sync.aligned.32x32b.x8.b32 [%0], " \
        "{%1,%2,%3,%4,%5,%6,%7,%8};" \
        :: "r"(ta), "r"((r)[0]), "r"((r)[1]), "r"((r)[2]), "r"((r)[3]), \
           "r"((r)[4]), "r"((r)[5]), "r"((r)[6]), "r"((r)[7]) : "memory")
#endif

// ------------------------- embedding ---------------------------------------
__global__ void __launch_bounds__(256) embed_kernel(
        const int* __restrict__ idx, const float* __restrict__ tok,
        const float* __restrict__ pos) {
    int row = blockIdx.x;
    int t = row & (NT - 1);
    int token = idx[row];
    const float4* t4 = (const float4*)(tok + (size_t)token * CD);
    const float4* p4 = (const float4*)(pos + (size_t)t * CD);
    float4 a = t4[threadIdx.x];
    float4 b = p4[threadIdx.x];
    a.x += b.x; a.y += b.y; a.z += b.z; a.w += b.w;
    ((float4*)(g_x + (size_t)row * CD))[threadIdx.x] = a;
}

// ------------------------- split write helper -------------------------------
__device__ __forceinline__ void write_split4(
        __nv_bfloat16* __restrict__ ph, __nv_bfloat16* __restrict__ pl,
        size_t o, float a0, float a1, float a2, float a3) {
    __nv_bfloat16 h0 = __float2bfloat16(a0), h1 = __float2bfloat16(a1);
    __nv_bfloat16 h2 = __float2bfloat16(a2), h3 = __float2bfloat16(a3);
    *(__nv_bfloat162*)&ph[o]     = __nv_bfloat162(h0, h1);
    *(__nv_bfloat162*)&ph[o + 2] = __nv_bfloat162(h2, h3);
    *(__nv_bfloat162*)&pl[o] = __nv_bfloat162(
        __float2bfloat16(a0 - __bfloat162float(h0)),
        __float2bfloat16(a1 - __bfloat162float(h1)));
    *(__nv_bfloat162*)&pl[o + 2] = __nv_bfloat162(
        __float2bfloat16(a2 - __bfloat162float(h2)),
        __float2bfloat16(a3 - __bfloat162float(h3)));
}

// ------------------------- layernorm (fused split) --------------------------
// mode 0: write bf16 hi/lo split to g_ah/g_al (pre-GEMM activations)
__global__ void __launch_bounds__(256) ln_kernel(
        const float* __restrict__ g, const float* __restrict__ b) {
    __shared__ float rs[8], rss[8];
    __shared__ float mean_s, rstd_s;
    const float* x = g_x;
    int row = blockIdx.x, tid = threadIdx.x;
    float4 v = ((const float4*)(x + (size_t)row * CD))[tid];
    float s  = v.x + v.y + v.z + v.w;
    float ss = v.x*v.x + v.y*v.y + v.z*v.z + v.w*v.w;
    #pragma unroll
    for (int o = 16; o; o >>= 1) {
        s  += __shfl_xor_sync(0xffffffffu, s,  o);
        ss += __shfl_xor_sync(0xffffffffu, ss, o);
    }
    if ((tid & 31) == 0) { rs[tid >> 5] = s; rss[tid >> 5] = ss; }
    __syncthreads();
    if (tid == 0) {
        float S = 0.f, SS = 0.f;
        #pragma unroll
        for (int i = 0; i < 8; i++) { S += rs[i]; SS += rss[i]; }
        float mean = S * (1.f / CD);
        float var  = SS * (1.f / CD) - mean * mean;
        mean_s = mean;
        rstd_s = rsqrtf(var + 1e-5f);
    }
    __syncthreads();
    float mean = mean_s, rstd = rstd_s;
    float4 gg = ((const float4*)g)[tid];
    float4 bb = ((const float4*)b)[tid];
    float o0 = (v.x - mean) * rstd * gg.x + bb.x;
    float o1 = (v.y - mean) * rstd * gg.y + bb.y;
    float o2 = (v.z - mean) * rstd * gg.z + bb.z;
    float o3 = (v.w - mean) * rstd * gg.w + bb.w;
    write_split4(g_ah, g_al, (size_t)row * CD + tid * 4, o0, o1, o2, o3);
}

// W[K,N] fp32 -> g_wh/g_wl at element offset woff, [N,K] bf16 (transposed)
__global__ void __launch_bounds__(256) split_w_kernel(
        const float* __restrict__ W, int K, int N, size_t woff) {
    __shared__ float t[32][33];
    int n0 = blockIdx.x * 32, k0 = blockIdx.y * 32;
    int tx = threadIdx.x & 31, ty = threadIdx.x >> 5;
    #pragma unroll
    for (int i = 0; i < 4; i++)
        t[ty + i * 8][tx] = W[(size_t)(k0 + ty + i * 8) * N + n0 + tx];
    __syncthreads();
    #pragma unroll
    for (int i = 0; i < 4; i++) {
        int n = ty + i * 8;
        float a = t[tx][n];
        __nv_bfloat16 hi = __float2bfloat16(a);
        float lo = a - __bfloat162float(hi);
        size_t o = woff + (size_t)(n0 + n) * K + k0 + tx;
        g_wh[o] = hi;
        g_wl[o] = __float2bfloat16(lo);
    }
}

// --------- bf16-split GEMM (256x256, BK=32, 3-stage cp.async) ---------------
#define BM 256
#define BN 256
#define BK 32
#define OFF_AH 0
#define OFF_AL 16384
#define OFF_BH 32768
#define OFF_BL 49152
#define STAGE  65536
#define NSTG   3
#define GEMM_SMEM (NSTG*STAGE + 2048)

__device__ __forceinline__ void load_stage_async(
        u32 stg, const __nv_bfloat16* __restrict__ ah,
        const __nv_bfloat16* __restrict__ al,
        const __nv_bfloat16* __restrict__ bh,
        const __nv_bfloat16* __restrict__ bl,
        int m0, int n0, int k0, int K, int tid) {
    int cc = tid & 3;
    int r0 = tid >> 2;
    #pragma unroll
    for (int j = 0; j < 4; j++) {
        int r = r0 + j * 64;
        u32 so = SWZ64((u32)(r * 64 + cc * 16));
        size_t aoff = (size_t)(m0 + r) * K + k0 + cc * 8;
        size_t boff = (size_t)(n0 + r) * K + k0 + cc * 8;
        CP_ASYNC16(stg + OFF_AH + so, (const void*)(ah + aoff));
        CP_ASYNC16(stg + OFF_AL + so, (const void*)(al + aoff));
        CP_ASYNC16(stg + OFF_BH + so, (const void*)(bh + boff));
        CP_ASYNC16(stg + OFF_BL + so, (const void*)(bl + boff));
    }
}

// EP=0: fp32 out. EP=1: +bias +res, fp32 out.
// EP=2: +bias, relu, split out to g_bh/g_bl. EP=3: QKV demux to g_q/g_k/g_v.
template<int EP>
__device__ __forceinline__ void ep_write4(
        float c0, float c1, float c2, float c3,
        const float* __restrict__ bias, const float* __restrict__ res,
        float* __restrict__ out, size_t m, int n, int N) {
    if (EP == 1 || EP == 2) {
        float4 bv = *(const float4*)&bias[n];
        c0 += bv.x; c1 += bv.y; c2 += bv.z; c3 += bv.w;
    }
    if (EP == 1) {
        float4 rv = *(const float4*)&res[m * N + n];
        c0 += rv.x; c1 += rv.y; c2 += rv.z; c3 += rv.w;
        *(float4*)&out[m * N + n] = make_float4(c0, c1, c2, c3);
    } else if (EP == 2) {
        c0 = fmaxf(c0, 0.f); c1 = fmaxf(c1, 0.f);
        c2 = fmaxf(c2, 0.f); c3 = fmaxf(c3, 0.f);
        write_split4(g_bh, g_bl, m * N + n, c0, c1, c2, c3);
    } else if (EP == 3) {
        int which = n >> 10;
        float* o = (which == 0) ? g_q : (which == 1) ? g_k : g_v;
        *(float4*)&o[m * CD + (n & 1023)] = make_float4(c0, c1, c2, c3);
    } else {
        *(float4*)&out[m * N + n] = make_float4(c0, c1, c2, c3);
    }
}

template<int EP>
__global__ void __launch_bounds__(256, 1) tcgemm_kernel(
        const float* __restrict__ bias, int asel, int rsel, int osel,
        int N, int K, size_t woff) {
    extern __shared__ char dsm[];
    u32 sb = (smem_u32(dsm) + 1023u) & ~1023u;
    int tid = threadIdx.x, wid = tid >> 5, lid = tid & 31;
    int m0 = blockIdx.y * BM, n0 = blockIdx.x * BN;
    const int NS = K / BK;
    const float* res = buf(rsel);
    float* out = buf(osel);
    const __nv_bfloat16* Ah = asel ? g_bh : g_ah;
    const __nv_bfloat16* Al = asel ? g_bl : g_al;
    const __nv_bfloat16* Bh = g_wh + woff;
    const __nv_bfloat16* Bl = g_wl + woff;

#if HAS_TCGEN05
    const u32 TM_PTR = sb + NSTG * STAGE;
    u32 mb[3] = {TM_PTR + 8, TM_PTR + 16, TM_PTR + 24};

    if (wid == 0) {
        asm volatile("tcgen05.alloc.cta_group::1.sync.aligned.shared::cta.b32 [%0], %1;"
                     :: "r"(TM_PTR), "r"(512u) : "memory");
        asm volatile("tcgen05.relinquish_alloc_permit.cta_group::1.sync.aligned;");
    }
    if (tid == 0) {
        mbar_init(mb[0], 1); mbar_init(mb[1], 1); mbar_init(mb[2], 1);
    }
    __syncthreads();
    u32 tmem;
    asm("ld.shared.b32 %0, [%1];" : "=r"(tmem) : "r"(TM_PTR));

    load_stage_async(sb, Ah, Al, Bh, Bl, m0, n0, 0, K, tid);
    CP_COMMIT();
    load_stage_async(sb + STAGE, Ah, Al, Bh, Bl, m0, n0, BK, K, tid);
    CP_COMMIT();

    u32 phx[3] = {0, 0, 0};
    for (int s = 0; s < NS; s++) {
        int b = s - (s / 3) * 3;
        u32 stg = sb + b * STAGE;
        if (s + 1 < NS) CP_WAIT1();
        else            CP_WAIT0();
        __syncthreads();
        if (wid == 0) {
            asm volatile("fence.proxy.async.shared::cta;" ::: "memory");
            if (elect1()) {
                u64 dah = MKDESC64(stg + OFF_AH);
                u64 dal = MKDESC64(stg + OFF_AL);
                u64 dbh = MKDESC64(stg + OFF_BH);
                u64 dbl = MKDESC64(stg + OFF_BL);
                #pragma unroll
                for (int half = 0; half < 2; half++) {
                    u32 d = tmem + half * 256;
                    u64 ha = dah + half * 512;   // +8192B = rows 128..255
                    u64 la = dal + half * 512;
                    #pragma unroll
                    for (int kk = 0; kk < 2; kk++) {
                        mma_f16_ss(d, ha + kk * 2, dbh + kk * 2, IDESC_256,
                                   (s == 0 && kk == 0) ? 0u : 1u);
                        mma_f16_ss(d, ha + kk * 2, dbl + kk * 2, IDESC_256, 1u);
                        mma_f16_ss(d, la + kk * 2, dbh + kk * 2, IDESC_256, 1u);
                    }
                }
                asm volatile(
                    "tcgen05.commit.cta_group::1.mbarrier::arrive::one.shared::cluster.b64 [%0];"
                    :: "r"(mb[b]) : "memory");
            }
        }
        if (s + 2 < NS) {
            int nb = (s + 2) - ((s + 2) / 3) * 3;
            if (s >= 1) { mbar_wait(mb[nb], phx[nb]); phx[nb] ^= 1u; }
            load_stage_async(sb + nb * STAGE, Ah, Al, Bh, Bl, m0, n0,
                             (s + 2) * BK, K, tid);
            CP_COMMIT();
        }
    }
    {
        int fb = (NS - 1) - ((NS - 1) / 3) * 3;
        mbar_wait(mb[fb], phx[fb]);
    }
    asm volatile("tcgen05.fence::after_thread_sync;" ::: "memory");

    {
        int half = wid >> 2, w4 = wid & 3;
        size_t m = (size_t)m0 + half * 128 + w4 * 32 + lid;
        u32 tbase = tmem + half * 256;
        for (int c0 = 0; c0 < BN; c0 += 32) {
            u32 r[32];
            LDTM32(r, tbase + c0);
            asm volatile("tcgen05.wait::ld.sync.aligned;" ::: "memory");
            #pragma unroll
            for (int q = 0; q < 8; q++) {
                int n = n0 + c0 + q * 4;
                ep_write4<EP>(__uint_as_float(r[q*4+0]), __uint_as_float(r[q*4+1]),
                              __uint_as_float(r[q*4+2]), __uint_as_float(r[q*4+3]),
                              bias, res, out, m, n, N);
            }
        }
    }
    __syncthreads();
    if (wid == 0) {
        asm volatile("tcgen05.dealloc.cta_group::1.sync.aligned.b32 %0, %1;"
                     :: "r"(tmem), "r"(512u));
    }
#else
    // Base-PTX fallback: never selected at runtime (sm_103a cubin exists).
    (void)sb; (void)lid; (void)wid;
    int r = tid;
    for (int jn4 = 0; jn4 < BN; jn4 += 4) {
        float c[4];
        #pragma unroll
        for (int jj = 0; jj < 4; jj++) {
            int n = n0 + jn4 + jj;
            float acc = 0.f;
            const __nv_bfloat16* ah = Ah + (size_t)(m0 + r) * K;
            const __nv_bfloat16* al = Al + (size_t)(m0 + r) * K;
            const __nv_bfloat16* bh = Bh + (size_t)n * K;
            const __nv_bfloat16* bl = Bl + (size_t)n * K;
            for (int k = 0; k < K; k++) {
                float av = __bfloat162float(ah[k]) + __bfloat162float(al[k]);
                float bv = __bfloat162float(bh[k]) + __bfloat162float(bl[k]);
                acc += av * bv;
            }
            c[jj] = acc;
        }
        ep_write4<EP>(c[0], c[1], c[2], c[3], bias, res, out,
                      (size_t)(m0 + r), n0 + jn4, N);
    }
#endif
}

// ------------------------- tensor-core flash attention ----------------------
#define ATT_QH 0
#define ATT_QL 16384
#define ATT_KH 32768
#define ATT_KL 49152
#define ATT_VH 65536
#define ATT_VL 81920
#define ATT_CTRL 98304
#define ATT_SMEM (98304 + 64)

#if HAS_TCGEN05
// load a 128x64 fp32 tile (row stride CD) -> split bf16 smem, SW128 rows of 128B
__device__ __forceinline__ void att_load_split(
        u32 dh, u32 dl, const float* __restrict__ g, int tid) {
    int cc = tid & 3, r0 = tid >> 2;
    #pragma unroll
    for (int j = 0; j < 4; j++) {
        int r = r0 + j * 32;
        const float* src = g + (size_t)r * CD + cc * 16;
        float f[16];
        #pragma unroll
        for (int i = 0; i < 4; i++) {
            float4 t = *(const float4*)(src + i * 4);
            f[i*4] = t.x; f[i*4+1] = t.y; f[i*4+2] = t.z; f[i*4+3] = t.w;
        }
        u32 hw[8], lw[8];
        #pragma unroll
        for (int i = 0; i < 8; i++) {
            float a = f[2*i], b = f[2*i+1];
            __nv_bfloat16 h0 = __float2bfloat16(a), h1 = __float2bfloat16(b);
            hw[i] = packbf2(a, b);
            lw[i] = packbf2(a - __bfloat162float(h0), b - __bfloat162float(h1));
        }
        u32 bo = (u32)(r * 128 + cc * 32);
        sts128(dh + SWZ128(bo),      make_uint4(hw[0], hw[1], hw[2], hw[3]));
        sts128(dh + SWZ128(bo + 16), make_uint4(hw[4], hw[5], hw[6], hw[7]));
        sts128(dl + SWZ128(bo),      make_uint4(lw[0], lw[1], lw[2], lw[3]));
        sts128(dl + SWZ128(bo + 16), make_uint4(lw[4], lw[5], lw[6], lw[7]));
    }
}

// load V 128x64 fp32 -> transposed split smem vt[d][key], blocked atoms:
// block0 keys 0-63 at 0, block1 keys 64-127 at 8192. rows = d (128B each).
__device__ __forceinline__ void att_load_split_vt(
        u32 dh, u32 dl, const float* __restrict__ g, int tid) {
    int cc = tid & 3, r0 = tid >> 2;
    #pragma unroll
    for (int j = 0; j < 4; j++) {
        int r = r0 + j * 32;              // key index
        const float* src = g + (size_t)r * CD + cc * 16;
        float f[16];
        #pragma unroll
        for (int i = 0; i < 4; i++) {
            float4 t = *(const float4*)(src + i * 4);
            f[i*4] = t.x; f[i*4+1] = t.y; f[i*4+2] = t.z; f[i*4+3] = t.w;
        }
        u32 blk = (r >= 64) ? 8192u : 0u;
        u32 rr = (u32)(r & 63) * 2;
        #pragma unroll
        for (int i = 0; i < 16; i++) {
            int d = cc * 16 + i;
            __nv_bfloat16 hv = __float2bfloat16(f[i]);
            __nv_bfloat16 lv = __float2bfloat16(f[i] - __bfloat162float(hv));
            u32 off = blk + (u32)d * 128 + rr;
            STS16(dh + SWZ128(off), __bfloat16_as_ushort(hv));
            STS16(dl + SWZ128(off), __bfloat16_as_ushort(lv));
        }
    }
}
#endif

__global__ void __launch_bounds__(128, 2) attn_kernel() {
#if HAS_TCGEN05
    extern __shared__ char dsm[];
    u32 sb = (smem_u32(dsm) + 1023u) & ~1023u;
    const u32 TM_PTR = sb + ATT_CTRL;
    const u32 MB_S = TM_PTR + 8, MB_PV = TM_PTR + 16;

    int tid = threadIdx.x, wid = tid >> 5;
    int bh = blockIdx.x, b = bh >> 4, h = bh & 15;
    int qb = blockIdx.y;
    const size_t base = (size_t)b * NT * CD + h * HSD;
    const u32 woff = (u32)(wid << 21);

    if (wid == 0) {
        asm volatile("tcgen05.alloc.cta_group::1.sync.aligned.shared::cta.b32 [%0], %1;"
                     :: "r"(TM_PTR), "r"(256u) : "memory");
        asm volatile("tcgen05.relinquish_alloc_permit.cta_group::1.sync.aligned;");
    }
    if (tid == 0) { mbar_init(MB_S, 1); mbar_init(MB_PV, 1); }
    __syncthreads();
    u32 tmem;
    asm("ld.shared.b32 %0, [%1];" : "=r"(tmem) : "r"(TM_PTR));

    att_load_split(sb + ATT_QH, sb + ATT_QL,
                   g_q + base + (size_t)(qb * 128) * CD, tid);

    float m_i = -1e30f, l_i = 0.f;
    float o[64];
    #pragma unroll
    for (int d = 0; d < 64; d++) o[d] = 0.f;
    const float scale = 0.125f;
    u32 ph_s = 0, ph_pv = 0;

    for (int kb = 0; kb <= qb; kb++) {
        __syncthreads();
        att_load_split(sb + ATT_KH, sb + ATT_KL,
                       g_k + base + (size_t)(kb * 128) * CD, tid);
        att_load_split_vt(sb + ATT_VH, sb + ATT_VL,
                          g_v + base + (size_t)(kb * 128) * CD, tid);
        asm volatile("fence.proxy.async.shared::cta;" ::: "memory");
        __syncthreads();

        if (wid == 0 && elect1()) {
            u64 dqh = MKDESC128(sb + ATT_QH), dql = MKDESC128(sb + ATT_QL);
            u64 dkh = MKDESC128(sb + ATT_KH), dkl = MKDESC128(sb + ATT_KL);
            #pragma unroll
            for (int ks = 0; ks < 4; ks++) {
                mma_f16_ss(tmem, dqh + ks*2, dkh + ks*2, IDESC_128, ks == 0 ? 0u : 1u);
                mma_f16_ss(tmem, dqh + ks*2, dkl + ks*2, IDESC_128, 1u);
                mma_f16_ss(tmem, dql + ks*2, dkh + ks*2, IDESC_128, 1u);
            }
            asm volatile(
                "tcgen05.commit.cta_group::1.mbarrier::arrive::one.shared::cluster.b64 [%0];"
                :: "r"(MB_S) : "memory");
        }
        mbar_wait(MB_S, ph_s); ph_s ^= 1u;
        asm volatile("tcgen05.fence::after_thread_sync;" ::: "memory");

        u32 sr[128];
        LDTM32(sr +  0, tmem +  0);
        LDTM32(sr + 32, tmem + 32);
        LDTM32(sr + 64, tmem + 64);
        LDTM32(sr + 96, tmem + 96);
        asm volatile("tcgen05.wait::ld.sync.aligned;" ::: "memory");

        float tm = -1e30f;
        if (kb == qb) {
            #pragma unroll
            for (int j = 0; j < 128; j++) {
                float v = (j > tid) ? -1e30f : __uint_as_float(sr[j]) * scale;
                sr[j] = __float_as_uint(v);
                tm = fmaxf(tm, v);
            }
        } else {
            #pragma unroll
            for (int j = 0; j < 128; j++) {
                float v = __uint_as_float(sr[j]) * scale;
                sr[j] = __float_as_uint(v);
                tm = fmaxf(tm, v);
            }
        }
        float nm = fmaxf(m_i, tm);
        float corr = __expf(m_i - nm);

        float lsum = 0.f;
        #pragma unroll
        for (int c = 0; c < 8; c++) {
            u32 hw[8], lw[8];
            #pragma unroll
            for (int i = 0; i < 8; i++) {
                int j = c * 16 + i * 2;
                float e0 = __expf(__uint_as_float(sr[j])     - nm);
                float e1 = __expf(__uint_as_float(sr[j + 1]) - nm);
                lsum += e0 + e1;
                __nv_bfloat16 h0 = __float2bfloat16(e0), h1 = __float2bfloat16(e1);
                hw[i] = packbf2(e0, e1);
                lw[i] = packbf2(e0 - __bfloat162float(h0), e1 - __bfloat162float(h1));
            }
            STTM8(tmem + 128 + c * 8 + woff, hw);
            STTM8(tmem + 192 + c * 8 + woff, lw);
        }
        asm volatile("tcgen05.wait::st.sync.aligned;" ::: "memory");
        l_i = l_i * corr + lsum;
        m_i = nm;
        asm volatile("tcgen05.fence::before_thread_sync;" ::: "memory");
        __syncthreads();

        if (wid == 0 && elect1()) {
            asm volatile("tcgen05.fence::after_thread_sync;" ::: "memory");
            u64 dvh = MKDESC128(sb + ATT_VH), dvl = MKDESC128(sb + ATT_VL);
            #pragma unroll
            for (int ks = 0; ks < 8; ks++) {
                u64 off = (ks < 4) ? (u64)(ks * 2) : (u64)(512 + (ks - 4) * 2);
                u32 aph = tmem + 128 + ks * 8;
                u32 apl = tmem + 192 + ks * 8;
                mma_f16_ts(tmem, aph, dvh + off, IDESC_64, ks == 0 ? 0u : 1u);
                mma_f16_ts(tmem, aph, dvl + off, IDESC_64, 1u);
                mma_f16_ts(tmem, apl, dvh + off, IDESC_64, 1u);
            }
            asm volatile(
                "tcgen05.commit.cta_group::1.mbarrier::arrive::one.shared::cluster.b64 [%0];"
                :: "r"(MB_PV) : "memory");
        }
        mbar_wait(MB_PV, ph_pv); ph_pv ^= 1u;
        asm volatile("tcgen05.fence::after_thread_sync;" ::: "memory");

        u32 org[64];
        LDTM32(org,      tmem +  0);
        LDTM32(org + 32, tmem + 32);
        asm volatile("tcgen05.wait::ld.sync.aligned;" ::: "memory");
        #pragma unroll
        for (int d = 0; d < 64; d++)
            o[d] = o[d] * corr + __uint_as_float(org[d]);
    }

    {
        float inv = 1.f / l_i;
        size_t obase = ((size_t)(b * NT + qb * 128 + tid)) * CD + h * HSD;
        #pragma unroll
        for (int g4 = 0; g4 < 16; g4++) {
            write_split4(g_ah, g_al, obase + g4 * 4,
                         o[g4*4+0] * inv, o[g4*4+1] * inv,
                         o[g4*4+2] * inv, o[g4*4+3] * inv);
        }
    }
    __syncthreads();
    if (wid == 0) {
        asm volatile("tcgen05.dealloc.cta_group::1.sync.aligned.b32 %0, %1;"
                     :: "r"(tmem), "r"(256u));
    }
#else
    int tid = threadIdx.x;
    int bh = blockIdx.x, b = bh >> 4, h = bh & 15;
    int t = blockIdx.y * 128 + tid;
    const size_t base = (size_t)b * NT * CD + h * HSD;
    const float* q = &g_q[base + (size_t)t * CD];
    float m = -1e30f, l = 0.f, o[64];
    for (int d = 0; d < 64; d++) o[d] = 0.f;
    for (int key = 0; key <= t; key++) {
        const float* kk = &g_k[base + (size_t)key * CD];
        float s = 0.f;
        for (int d = 0; d < 64; d++) s += q[d] * kk[d];
        s *= 0.125f;
        float nm = fmaxf(m, s);
        float corr = __expf(m - nm), e = __expf(s - nm);
        l = l * corr + e; m = nm;
        const float* vv = &g_v[base + (size_t)key * CD];
        for (int d = 0; d < 64; d++) o[d] = o[d] * corr + e * vv[d];
    }
    float inv = 1.f / l;
    size_t obase = ((size_t)(b * NT + t)) * CD + h * HSD;
    for (int g4 = 0; g4 < 16; g4++)
        write_split4(g_ah, g_al, obase + g4 * 4,
                     o[g4*4+0]*inv, o[g4*4+1]*inv, o[g4*4+2]*inv, o[g4*4+3]*inv);
#endif
}

// ---------------- LM head (N=67) with fused final LayerNorm -----------------
__global__ void __launch_bounds__(128) lm_kernel(
        const float* __restrict__ W, const float* __restrict__ bias,
        const float* __restrict__ lg, const float* __restrict__ lb,
        float* __restrict__ out) {
    __shared__ float hs[CD];
    __shared__ float rs[4], rss[4];
    __shared__ float mean_s, rstd_s;
    int row = blockIdx.x;
    int tid = threadIdx.x;
    const float* x = g_x + (size_t)row * CD;
    float4 v0 = ((const float4*)x)[tid];
    float4 v1 = ((const float4*)x)[tid + 128];
    float s  = v0.x + v0.y + v0.z + v0.w + v1.x + v1.y + v1.z + v1.w;
    float ss = v0.x*v0.x + v0.y*v0.y + v0.z*v0.z + v0.w*v0.w
             + v1.x*v1.x + v1.y*v1.y + v1.z*v1.z + v1.w*v1.w;
    #pragma unroll
    for (int o = 16; o; o >>= 1) {
        s  += __shfl_xor_sync(0xffffffffu, s,  o);
        ss += __shfl_xor_sync(0xffffffffu, ss, o);
    }
    if ((tid & 31) == 0) { rs[tid >> 5] = s; rss[tid >> 5] = ss; }
    __syncthreads();
    if (tid == 0) {
        float S = rs[0] + rs[1] + rs[2] + rs[3];
        float SS = rss[0] + rss[1] + rss[2] + rss[3];
        float mean = S * (1.f / CD);
        float var  = SS * (1.f / CD) - mean * mean;
        mean_s = mean;
        rstd_s = rsqrtf(var + 1e-5f);
    }
    __syncthreads();
    float mean = mean_s, rstd = rstd_s;
    {
        float4 g0 = ((const float4*)lg)[tid];
        float4 b0 = ((const float4*)lb)[tid];
        float4 g1 = ((const float4*)lg)[tid + 128];
        float4 b1 = ((const float4*)lb)[tid + 128];
        float4 o0, o1;
        o0.x = (v0.x - mean) * rstd * g0.x + b0.x;
        o0.y = (v0.y - mean) * rstd * g0.y + b0.y;
        o0.z = (v0.z - mean) * rstd * g0.z + b0.z;
        o0.w = (v0.w - mean) * rstd * g0.w + b0.w;
        o1.x = (v1.x - mean) * rstd * g1.x + b1.x;
        o1.y = (v1.y - mean) * rstd * g1.y + b1.y;
        o1.z = (v1.z - mean) * rstd * g1.z + b1.z;
        o1.w = (v1.w - mean) * rstd * g1.w + b1.w;
        ((float4*)hs)[tid]       = o0;
        ((float4*)hs)[tid + 128] = o1;
    }
    __syncthreads();
    if (tid < NV) {
        float a0 = 0.f, a1 = 0.f, a2 = 0.f, a3 = 0.f;
        #pragma unroll 4
        for (int kk = 0; kk < CD; kk += 4) {
            a0 += hs[kk + 0] * W[(kk + 0) * NV + tid];
            a1 += hs[kk + 1] * W[(kk + 1) * NV + tid];
            a2 += hs[kk + 2] * W[(kk + 2) * NV + tid];
            a3 += hs[kk + 3] * W[(kk + 3) * NV + tid];
        }
        out[(size_t)row * NV + tid] = bias[tid] + ((a0 + a1) + (a2 + a3));
    }
}

// ------------------------- launch ------------------------------------------
static void split_layer(int l, cudaStream_t st,
                        const float* Wq, const float* Wk, const float* Wv,
                        const float* Wo, const float* W1, const float* W2) {
    dim3 wC(CD / 32, CD / 32);
    dim3 w1g(FFD / 32, CD / 32);
    dim3 w2g(CD / 32, FFD / 32);
    size_t p = (size_t)(l & 1) * WSEG;
    split_w_kernel<<<wC, 256, 0, st>>>(Wq + (size_t)l * CD * CD, CD, CD, p + WOFF_QKV);
    split_w_kernel<<<wC, 256, 0, st>>>(Wk + (size_t)l * CD * CD, CD, CD, p + WOFF_QKV + 1024 * 1024);
    split_w_kernel<<<wC, 256, 0, st>>>(Wv + (size_t)l * CD * CD, CD, CD, p + WOFF_QKV + 2 * 1024 * 1024);
    split_w_kernel<<<wC, 256, 0, st>>>(Wo + (size_t)l * CD * CD, CD, CD, p + WOFF_WO);
    split_w_kernel<<<w1g, 256, 0, st>>>(W1 + (size_t)l * CD * FFD, CD, FFD, p + WOFF_W1);
    split_w_kernel<<<w2g, 256, 0, st>>>(W2 + (size_t)l * FFD * CD, FFD, CD, p + WOFF_W2);
}

extern "C" void kernel_launch(void* const* d_in, const int* in_sizes, int n_in,
                              void* d_out, int out_size) {
    const int*   idx  = (const int*)  d_in[0];
    const float* tok  = (const float*)d_in[1];
    const float* pos  = (const float*)d_in[2];
    const float* Wq   = (const float*)d_in[3];
    const float* Wk   = (const float*)d_in[4];
    const float* Wv   = (const float*)d_in[5];
    const float* Wo   = (const float*)d_in[6];
    const float* bo   = (const float*)d_in[7];
    const float* ln1g = (const float*)d_in[8];
    const float* ln1b = (const float*)d_in[9];
    const float* ln2g = (const float*)d_in[10];
    const float* ln2b = (const float*)d_in[11];
    const float* W1   = (const float*)d_in[12];
    const float* b1   = (const float*)d_in[13];
    const float* W2   = (const float*)d_in[14];
    const float* b2   = (const float*)d_in[15];
    const float* lnfg = (const float*)d_in[16];
    const float* lnfb = (const float*)d_in[17];
    const float* Wlm  = (const float*)d_in[18];
    const float* blm  = (const float*)d_in[19];
    float* out = (float*)d_out;

    // side stream + events (host-side objects, created once; no device memory)
    static cudaStream_t s2 = nullptr;
    static cudaEvent_t evA[NL], evB[NL];
    if (!s2) {
        cudaStreamCreateWithFlags(&s2, cudaStreamNonBlocking);
        for (int i = 0; i < NL; i++) {
            cudaEventCreateWithFlags(&evA[i], cudaEventDisableTiming);
            cudaEventCreateWithFlags(&evB[i], cudaEventDisableTiming);
        }
    }

    cudaFuncSetAttribute(tcgemm_kernel<0>,
                         cudaFuncAttributeMaxDynamicSharedMemorySize, GEMM_SMEM);
    cudaFuncSetAttribute(tcgemm_kernel<1>,
                         cudaFuncAttributeMaxDynamicSharedMemorySize, GEMM_SMEM);
    cudaFuncSetAttribute(tcgemm_kernel<2>,
                         cudaFuncAttributeMaxDynamicSharedMemorySize, GEMM_SMEM);
    cudaFuncSetAttribute(tcgemm_kernel<3>,
                         cudaFuncAttributeMaxDynamicSharedMemorySize, GEMM_SMEM);
    cudaFuncSetAttribute(attn_kernel,
                         cudaFuncAttributeMaxDynamicSharedMemorySize, ATT_SMEM);

    dim3 gC(CD / BN, NM / BM);        // (4, 32)
    dim3 gQKV(3 * CD / BN, NM / BM);  // (12, 32)
    dim3 gF(FFD / BN, NM / BM);       // (16, 32)
    dim3 gA(NB * NH, NT / 128);       // (128, 8)

    embed_kernel<<<NM, 256>>>(idx, tok, pos);
    split_layer(0, 0, Wq, Wk, Wv, Wo, W1, W2);   // layer 0 weights: exposed

    for (int l = 0; l < NL; l++) {
        size_t p = (size_t)(l & 1) * WSEG;

        // fork: prefetch layer l+1's weights on side stream into other segment
        if (l + 1 < NL) {
            cudaEventRecord(evA[l], 0);
            cudaStreamWaitEvent(s2, evA[l], 0);
            split_layer(l + 1, s2, Wq, Wk, Wv, Wo, W1, W2);
            cudaEventRecord(evB[l], s2);
        }

        ln_kernel<<<NM, 256>>>(ln1g + (size_t)l * CD, ln1b + (size_t)l * CD);
        tcgemm_kernel<3><<<gQKV, 256, GEMM_SMEM>>>(
            nullptr, 0, 0, 0, 3 * CD, CD, p + WOFF_QKV);
        attn_kernel<<<gA, 128, ATT_SMEM>>>();
        tcgemm_kernel<1><<<gC, 256, GEMM_SMEM>>>(
            bo + (size_t)l * CD, 0, 0, 0, CD, CD, p + WOFF_WO);
        ln_kernel<<<NM, 256>>>(ln2g + (size_t)l * CD, ln2b + (size_t)l * CD);
        tcgemm_kernel<2><<<gF, 256, GEMM_SMEM>>>(
            b1 + (size_t)l * FFD, 0, 0, 0, FFD, CD, p + WOFF_W1);
        tcgemm_kernel<1><<<gC, 256, GEMM_SMEM>>>(
            b2 + (size_t)l * CD, 1, 0, 0, CD, FFD, p + WOFF_W2);

        // join: next layer's QKV GEMM needs the prefetched weights
        if (l + 1 < NL) cudaStreamWaitEvent(0, evB[l], 0);
    }
    lm_kernel<<<NM, 128>>>(Wlm, blm, lnfg, lnfb, out);
}

// round 16
// speedup vs baseline: 1.3783x; 1.0060x over previous
#include <cuda_runtime.h>
#include <cuda_bf16.h>
#include <cstdint>
#include <cstddef>

#define NL 6
#define NH 16
#define CD 1024
#define HSD 64
#define FFD 4096
#define NV 67
#define NB 8
#define NT 1024
#define NM (NB*NT)   // 8192 rows

typedef unsigned long long u64;
typedef unsigned int u32;

// Arch-specific feature gate: tcgen05 only exists in the sm_103a cubin pass.
#if defined(__CUDA_ARCH__) && (defined(__CUDA_ARCH_FEAT_SM103_ALL) || defined(__CUDA_ARCH_SPECIFIC__))
#define HAS_TCGEN05 1
#else
#define HAS_TCGEN05 0
#endif

// weight segment layout (elements): QKV@0 (3M), Wo@3M (1M), W1@4M (4M), W2@8M (4M)
#define WSEG  12582912ull            // 12M elements per layer-parity segment
#define WOFF_QKV 0ull
#define WOFF_WO  3145728ull
#define WOFF_W1  4194304ull
#define WOFF_W2  8388608ull

// ------------------------- scratch (device globals, no allocation) ---------
__device__ float g_x [(size_t)NM*CD];
__device__ float g_h [(size_t)NM*CD];
__device__ float g_q [(size_t)NM*CD];
__device__ float g_k [(size_t)NM*CD];
__device__ float g_v [(size_t)NM*CD];
// bf16 split buffers: two activation pairs (ping/pong) + double-buffered weights
__device__ __nv_bfloat16 g_ah[(size_t)NM*FFD];
__device__ __nv_bfloat16 g_al[(size_t)NM*FFD];
__device__ __nv_bfloat16 g_bh[(size_t)NM*FFD];
__device__ __nv_bfloat16 g_bl[(size_t)NM*FFD];
__device__ __nv_bfloat16 g_wh[2*WSEG];
__device__ __nv_bfloat16 g_wl[2*WSEG];

__device__ __forceinline__ float* buf(int which) {
    switch (which) {
        case 0: return g_x;
        case 1: return g_h;
        case 2: return g_q;
        case 3: return g_k;
        default: return g_v;
    }
}

// ------------------------- PTX helpers -------------------------------------
__device__ __forceinline__ u32 smem_u32(const void* p) {
    u32 a;
    asm("{ .reg .u64 t; cvta.to.shared.u64 t, %1; cvt.u32.u64 %0, t; }"
        : "=r"(a) : "l"(p));
    return a;
}
#define SWZ64(o)  ((o) ^ (((o) >> 3) & 0x30))
#define SWZ128(o) ((o) ^ (((o) >> 3) & 0x70))

#define CP_ASYNC16(dst, src) \
    asm volatile("cp.async.cg.shared.global [%0], [%1], 16;" \
                 :: "r"(dst), "l"(src) : "memory")
#define CP_COMMIT() asm volatile("cp.async.commit_group;" ::: "memory")
#define CP_WAIT0()  asm volatile("cp.async.wait_group 0;" ::: "memory")
#define CP_WAIT1()  asm volatile("cp.async.wait_group 1;" ::: "memory")

#define STS16(addr, v) \
    asm volatile("st.shared.u16 [%0], %1;" :: "r"(addr), "h"(v) : "memory")

__device__ __forceinline__ void sts128(u32 addr, uint4 v) {
    asm volatile("st.shared.v4.b32 [%0], {%1,%2,%3,%4};"
                 :: "r"(addr), "r"(v.x), "r"(v.y), "r"(v.z), "r"(v.w) : "memory");
}

__device__ __forceinline__ u32 packbf2(float a, float b) {
    __nv_bfloat162 t(__float2bfloat16(a), __float2bfloat16(b));
    return *(u32*)&t;
}

__device__ __forceinline__ void mbar_init(u32 addr, u32 cnt) {
    asm volatile("mbarrier.init.shared.b64 [%0], %1;" :: "r"(addr), "r"(cnt) : "memory");
}
__device__ __forceinline__ void mbar_wait(u32 addr, u32 phase) {
    asm volatile("{\n\t.reg .pred P;\n\t"
        "W_%=:\n\t"
        "mbarrier.try_wait.parity.acquire.cta.shared::cta.b64 P, [%0], %1, 0x989680;\n\t"
        "@P bra.uni D_%=;\n\t"
        "bra.uni W_%=;\n\t"
        "D_%=:\n\t}"
        :: "r"(addr), "r"(phase) : "memory");
}

#if HAS_TCGEN05
__device__ __forceinline__ u32 elect1() {
    u32 pred;
    asm volatile("{\n\t.reg .pred p;\n\telect.sync _|p, 0xFFFFFFFF;\n\t"
                 "selp.b32 %0, 1, 0, p;\n\t}" : "=r"(pred));
    return pred;
}
__device__ __forceinline__ void mma_f16_ss(u32 d, u64 ad, u64 bd, u32 idesc, u32 acc) {
    asm volatile("{\n\t.reg .pred p;\n\tsetp.ne.u32 p, %5, 0;\n\t"
        "tcgen05.mma.cta_group::1.kind::f16 [%0], %1, %2, %3, {%4,%4,%4,%4}, p;\n\t}"
        :: "r"(d), "l"(ad), "l"(bd), "r"(idesc), "r"(0u), "r"(acc) : "memory");
}
__device__ __forceinline__ void mma_f16_ts(u32 d, u32 a, u64 bd, u32 idesc, u32 acc) {
    asm volatile("{\n\t.reg .pred p;\n\tsetp.ne.u32 p, %5, 0;\n\t"
        "tcgen05.mma.cta_group::1.kind::f16 [%0], [%1], %2, %3, {%4,%4,%4,%4}, p;\n\t}"
        :: "r"(d), "r"(a), "l"(bd), "r"(idesc), "r"(0u), "r"(acc) : "memory");
}
// SW64 desc (GEMM): layout=4, version=1, SBO=32, LBO=1
#define DESC64_BASE ((4ull<<61)|(1ull<<46)|(32ull<<32)|(1ull<<16))
#define MKDESC64(a) (DESC64_BASE | ((u64)((a) >> 4) & 0x3FFFull))
// SW128 desc (attention): layout=2, version=1, SBO=64, LBO=1
#define DESC128_BASE ((2ull<<61)|(1ull<<46)|(64ull<<32)|(1ull<<16))
#define MKDESC128(a) (DESC128_BASE | ((u64)((a) >> 4) & 0x3FFFull))
#define IDESC_256 0x8400490u   // F32 acc, BF16xBF16, M=128, N=256
#define IDESC_128 0x8200490u   // M=128, N=128
#define IDESC_64  0x8100490u   // M=128, N=64

#define LDTM32(r, ta) \
    asm volatile("tcgen05.ld.sync.aligned.32x32b.x32.b32 " \
        "{%0,%1,%2,%3,%4,%5,%6,%7,%8,%9,%10,%11,%12,%13,%14,%15," \
        "%16,%17,%18,%19,%20,%21,%22,%23,%24,%25,%26,%27,%28,%29,%30,%31}, [%32];" \
        : "=r"((r)[0]),"=r"((r)[1]),"=r"((r)[2]),"=r"((r)[3]), \
          "=r"((r)[4]),"=r"((r)[5]),"=r"((r)[6]),"=r"((r)[7]), \
          "=r"((r)[8]),"=r"((r)[9]),"=r"((r)[10]),"=r"((r)[11]), \
          "=r"((r)[12]),"=r"((r)[13]),"=r"((r)[14]),"=r"((r)[15]), \
          "=r"((r)[16]),"=r"((r)[17]),"=r"((r)[18]),"=r"((r)[19]), \
          "=r"((r)[20]),"=r"((r)[21]),"=r"((r)[22]),"=r"((r)[23]), \
          "=r"((r)[24]),"=r"((r)[25]),"=r"((r)[26]),"=r"((r)[27]), \
          "=r"((r)[28]),"=r"((r)[29]),"=r"((r)[30]),"=r"((r)[31]) \
        : "r"(ta))

#define STTM8(ta, r) \
    asm volatile("tcgen05.st.sync.aligned.32x32b.x8.b32 [%0], " \
        "{%1,%2,%3,%4,%5,%6,%7,%8};" \
        :: "r"(ta), "r"((r)[0]), "r"((r)[1]), "r"((r)[2]), "r"((r)[3]), \
           "r"((r)[4]), "r"((r)[5]), "r"((r)[6]), "r"((r)[7]) : "memory")
#endif

// ------------------------- embedding ---------------------------------------
__global__ void __launch_bounds__(256) embed_kernel(
        const int* __restrict__ idx, const float* __restrict__ tok,
        const float* __restrict__ pos) {
    int row = blockIdx.x;
    int t = row & (NT - 1);
    int token = idx[row];
    const float4* t4 = (const float4*)(tok + (size_t)token * CD);
    const float4* p4 = (const float4*)(pos + (size_t)t * CD);
    float4 a = t4[threadIdx.x];
    float4 b = p4[threadIdx.x];
    a.x += b.x; a.y += b.y; a.z += b.z; a.w += b.w;
    ((float4*)(g_x + (size_t)row * CD))[threadIdx.x] = a;
}

// ------------------------- split write helper -------------------------------
__device__ __forceinline__ void write_split4(
        __nv_bfloat16* __restrict__ ph, __nv_bfloat16* __restrict__ pl,
        size_t o, float a0, float a1, float a2, float a3) {
    __nv_bfloat16 h0 = __float2bfloat16(a0), h1 = __float2bfloat16(a1);
    __nv_bfloat16 h2 = __float2bfloat16(a2), h3 = __float2bfloat16(a3);
    *(__nv_bfloat162*)&ph[o]     = __nv_bfloat162(h0, h1);
    *(__nv_bfloat162*)&ph[o + 2] = __nv_bfloat162(h2, h3);
    *(__nv_bfloat162*)&pl[o] = __nv_bfloat162(
        __float2bfloat16(a0 - __bfloat162float(h0)),
        __float2bfloat16(a1 - __bfloat162float(h1)));
    *(__nv_bfloat162*)&pl[o + 2] = __nv_bfloat162(
        __float2bfloat16(a2 - __bfloat162float(h2)),
        __float2bfloat16(a3 - __bfloat162float(h3)));
}

// ------------------------- layernorm (fused split) --------------------------
__global__ void __launch_bounds__(256) ln_kernel(
        const float* __restrict__ g, const float* __restrict__ b) {
    __shared__ float rs[8], rss[8];
    __shared__ float mean_s, rstd_s;
    const float* x = g_x;
    int row = blockIdx.x, tid = threadIdx.x;
    float4 v = ((const float4*)(x + (size_t)row * CD))[tid];
    float s  = v.x + v.y + v.z + v.w;
    float ss = v.x*v.x + v.y*v.y + v.z*v.z + v.w*v.w;
    #pragma unroll
    for (int o = 16; o; o >>= 1) {
        s  += __shfl_xor_sync(0xffffffffu, s,  o);
        ss += __shfl_xor_sync(0xffffffffu, ss, o);
    }
    if ((tid & 31) == 0) { rs[tid >> 5] = s; rss[tid >> 5] = ss; }
    __syncthreads();
    if (tid == 0) {
        float S = 0.f, SS = 0.f;
        #pragma unroll
        for (int i = 0; i < 8; i++) { S += rs[i]; SS += rss[i]; }
        float mean = S * (1.f / CD);
        float var  = SS * (1.f / CD) - mean * mean;
        mean_s = mean;
        rstd_s = rsqrtf(var + 1e-5f);
    }
    __syncthreads();
    float mean = mean_s, rstd = rstd_s;
    float4 gg = ((const float4*)g)[tid];
    float4 bb = ((const float4*)b)[tid];
    float o0 = (v.x - mean) * rstd * gg.x + bb.x;
    float o1 = (v.y - mean) * rstd * gg.y + bb.y;
    float o2 = (v.z - mean) * rstd * gg.z + bb.z;
    float o3 = (v.w - mean) * rstd * gg.w + bb.w;
    write_split4(g_ah, g_al, (size_t)row * CD + tid * 4, o0, o1, o2, o3);
}

// W[K,N] fp32 -> g_wh/g_wl at element offset woff, [N,K] bf16 (transposed)
__global__ void __launch_bounds__(256) split_w_kernel(
        const float* __restrict__ W, int K, int N, size_t woff) {
    __shared__ float t[32][33];
    int n0 = blockIdx.x * 32, k0 = blockIdx.y * 32;
    int tx = threadIdx.x & 31, ty = threadIdx.x >> 5;
    #pragma unroll
    for (int i = 0; i < 4; i++)
        t[ty + i * 8][tx] = W[(size_t)(k0 + ty + i * 8) * N + n0 + tx];
    __syncthreads();
    #pragma unroll
    for (int i = 0; i < 4; i++) {
        int n = ty + i * 8;
        float a = t[tx][n];
        __nv_bfloat16 hi = __float2bfloat16(a);
        float lo = a - __bfloat162float(hi);
        size_t o = woff + (size_t)(n0 + n) * K + k0 + tx;
        g_wh[o] = hi;
        g_wl[o] = __float2bfloat16(lo);
    }
}

// --------- bf16-split GEMM (256x256, BK=32, 3-stage cp.async) ---------------
#define BM 256
#define BN 256
#define BK 32
#define OFF_AH 0
#define OFF_AL 16384
#define OFF_BH 32768
#define OFF_BL 49152
#define STAGE  65536
#define NSTG   3
#define GEMM_SMEM (NSTG*STAGE + 2048)

__device__ __forceinline__ void load_stage_async(
        u32 stg, const __nv_bfloat16* __restrict__ ah,
        const __nv_bfloat16* __restrict__ al,
        const __nv_bfloat16* __restrict__ bh,
        const __nv_bfloat16* __restrict__ bl,
        int m0, int n0, int k0, int K, int tid) {
    int cc = tid & 3;
    int r0 = tid >> 2;
    #pragma unroll
    for (int j = 0; j < 4; j++) {
        int r = r0 + j * 64;
        u32 so = SWZ64((u32)(r * 64 + cc * 16));
        size_t aoff = (size_t)(m0 + r) * K + k0 + cc * 8;
        size_t boff = (size_t)(n0 + r) * K + k0 + cc * 8;
        CP_ASYNC16(stg + OFF_AH + so, (const void*)(ah + aoff));
        CP_ASYNC16(stg + OFF_AL + so, (const void*)(al + aoff));
        CP_ASYNC16(stg + OFF_BH + so, (const void*)(bh + boff));
        CP_ASYNC16(stg + OFF_BL + so, (const void*)(bl + boff));
    }
}

// EP=0: fp32 out. EP=1: +bias +res, fp32 out.
// EP=2: +bias, relu, split out to g_bh/g_bl. EP=3: QKV demux to g_q/g_k/g_v.
template<int EP>
__device__ __forceinline__ void ep_write4(
        float c0, float c1, float c2, float c3,
        const float* __restrict__ bias, const float* __restrict__ res,
        float* __restrict__ out, size_t m, int n, int N) {
    if (EP == 1 || EP == 2) {
        float4 bv = *(const float4*)&bias[n];
        c0 += bv.x; c1 += bv.y; c2 += bv.z; c3 += bv.w;
    }
    if (EP == 1) {
        float4 rv = *(const float4*)&res[m * N + n];
        c0 += rv.x; c1 += rv.y; c2 += rv.z; c3 += rv.w;
        *(float4*)&out[m * N + n] = make_float4(c0, c1, c2, c3);
    } else if (EP == 2) {
        c0 = fmaxf(c0, 0.f); c1 = fmaxf(c1, 0.f);
        c2 = fmaxf(c2, 0.f); c3 = fmaxf(c3, 0.f);
        write_split4(g_bh, g_bl, m * N + n, c0, c1, c2, c3);
    } else if (EP == 3) {
        int which = n >> 10;
        float* o = (which == 0) ? g_q : (which == 1) ? g_k : g_v;
        *(float4*)&o[m * CD + (n & 1023)] = make_float4(c0, c1, c2, c3);
    } else {
        *(float4*)&out[m * N + n] = make_float4(c0, c1, c2, c3);
    }
}

template<int EP>
__global__ void __launch_bounds__(256, 1) tcgemm_kernel(
        const float* __restrict__ bias, int asel, int rsel, int osel,
        int N, int K, size_t woff) {
    extern __shared__ char dsm[];
    u32 sb = (smem_u32(dsm) + 1023u) & ~1023u;
    int tid = threadIdx.x, wid = tid >> 5, lid = tid & 31;
    int m0 = blockIdx.y * BM, n0 = blockIdx.x * BN;
    const int NS = K / BK;
    const float* res = buf(rsel);
    float* out = buf(osel);
    const __nv_bfloat16* Ah = asel ? g_bh : g_ah;
    const __nv_bfloat16* Al = asel ? g_bl : g_al;
    const __nv_bfloat16* Bh = g_wh + woff;
    const __nv_bfloat16* Bl = g_wl + woff;

#if HAS_TCGEN05
    const u32 TM_PTR = sb + NSTG * STAGE;
    u32 mb[3] = {TM_PTR + 8, TM_PTR + 16, TM_PTR + 24};

    if (wid == 0) {
        asm volatile("tcgen05.alloc.cta_group::1.sync.aligned.shared::cta.b32 [%0], %1;"
                     :: "r"(TM_PTR), "r"(512u) : "memory");
        asm volatile("tcgen05.relinquish_alloc_permit.cta_group::1.sync.aligned;");
    }
    if (tid == 0) {
        mbar_init(mb[0], 1); mbar_init(mb[1], 1); mbar_init(mb[2], 1);
    }
    __syncthreads();
    u32 tmem;
    asm("ld.shared.b32 %0, [%1];" : "=r"(tmem) : "r"(TM_PTR));

    load_stage_async(sb, Ah, Al, Bh, Bl, m0, n0, 0, K, tid);
    CP_COMMIT();
    load_stage_async(sb + STAGE, Ah, Al, Bh, Bl, m0, n0, BK, K, tid);
    CP_COMMIT();

    u32 phx[3] = {0, 0, 0};
    for (int s = 0; s < NS; s++) {
        int b = s - (s / 3) * 3;
        u32 stg = sb + b * STAGE;
        if (s + 1 < NS) CP_WAIT1();
        else            CP_WAIT0();
        __syncthreads();
        if (wid == 0) {
            asm volatile("fence.proxy.async.shared::cta;" ::: "memory");
            if (elect1()) {
                u64 dah = MKDESC64(stg + OFF_AH);
                u64 dal = MKDESC64(stg + OFF_AL);
                u64 dbh = MKDESC64(stg + OFF_BH);
                u64 dbl = MKDESC64(stg + OFF_BL);
                #pragma unroll
                for (int half = 0; half < 2; half++) {
                    u32 d = tmem + half * 256;
                    u64 ha = dah + half * 512;   // +8192B = rows 128..255
                    u64 la = dal + half * 512;
                    #pragma unroll
                    for (int kk = 0; kk < 2; kk++) {
                        mma_f16_ss(d, ha + kk * 2, dbh + kk * 2, IDESC_256,
                                   (s == 0 && kk == 0) ? 0u : 1u);
                        mma_f16_ss(d, ha + kk * 2, dbl + kk * 2, IDESC_256, 1u);
                        mma_f16_ss(d, la + kk * 2, dbh + kk * 2, IDESC_256, 1u);
                    }
                }
                asm volatile(
                    "tcgen05.commit.cta_group::1.mbarrier::arrive::one.shared::cluster.b64 [%0];"
                    :: "r"(mb[b]) : "memory");
            }
        }
        if (s + 2 < NS) {
            int nb = (s + 2) - ((s + 2) / 3) * 3;
            if (s >= 1) { mbar_wait(mb[nb], phx[nb]); phx[nb] ^= 1u; }
            load_stage_async(sb + nb * STAGE, Ah, Al, Bh, Bl, m0, n0,
                             (s + 2) * BK, K, tid);
            CP_COMMIT();
        }
    }
    {
        int fb = (NS - 1) - ((NS - 1) / 3) * 3;
        mbar_wait(mb[fb], phx[fb]);
    }
    asm volatile("tcgen05.fence::after_thread_sync;" ::: "memory");

    {
        int half = wid >> 2, w4 = wid & 3;
        size_t m = (size_t)m0 + half * 128 + w4 * 32 + lid;
        u32 tbase = tmem + half * 256;
        for (int c0 = 0; c0 < BN; c0 += 32) {
            u32 r[32];
            LDTM32(r, tbase + c0);
            asm volatile("tcgen05.wait::ld.sync.aligned;" ::: "memory");
            #pragma unroll
            for (int q = 0; q < 8; q++) {
                int n = n0 + c0 + q * 4;
                ep_write4<EP>(__uint_as_float(r[q*4+0]), __uint_as_float(r[q*4+1]),
                              __uint_as_float(r[q*4+2]), __uint_as_float(r[q*4+3]),
                              bias, res, out, m, n, N);
            }
        }
    }
    __syncthreads();
    if (wid == 0) {
        asm volatile("tcgen05.dealloc.cta_group::1.sync.aligned.b32 %0, %1;"
                     :: "r"(tmem), "r"(512u));
    }
#else
    // Base-PTX fallback: never selected at runtime (sm_103a cubin exists).
    (void)sb; (void)lid; (void)wid;
    int r = tid;
    for (int jn4 = 0; jn4 < BN; jn4 += 4) {
        float c[4];
        #pragma unroll
        for (int jj = 0; jj < 4; jj++) {
            int n = n0 + jn4 + jj;
            float acc = 0.f;
            const __nv_bfloat16* ah = Ah + (size_t)(m0 + r) * K;
            const __nv_bfloat16* al = Al + (size_t)(m0 + r) * K;
            const __nv_bfloat16* bh = Bh + (size_t)n * K;
            const __nv_bfloat16* bl = Bl + (size_t)n * K;
            for (int k = 0; k < K; k++) {
                float av = __bfloat162float(ah[k]) + __bfloat162float(al[k]);
                float bv = __bfloat162float(bh[k]) + __bfloat162float(bl[k]);
                acc += av * bv;
            }
            c[jj] = acc;
        }
        ep_write4<EP>(c[0], c[1], c[2], c[3], bias, res, out,
                      (size_t)(m0 + r), n0 + jn4, N);
    }
#endif
}

// ------------------------- tensor-core flash attention ----------------------
#define ATT_QH 0
#define ATT_QL 16384
#define ATT_KH 32768
#define ATT_KL 49152
#define ATT_VH 65536
#define ATT_VL 81920
#define ATT_CTRL 98304
#define ATT_SMEM (98304 + 64)

#if HAS_TCGEN05
// load a 128x64 fp32 tile (row stride CD) -> split bf16 smem, SW128 rows of 128B
__device__ __forceinline__ void att_load_split(
        u32 dh, u32 dl, const float* __restrict__ g, int tid) {
    int cc = tid & 3, r0 = tid >> 2;
    #pragma unroll
    for (int j = 0; j < 4; j++) {
        int r = r0 + j * 32;
        const float* src = g + (size_t)r * CD + cc * 16;
        float f[16];
        #pragma unroll
        for (int i = 0; i < 4; i++) {
            float4 t = *(const float4*)(src + i * 4);
            f[i*4] = t.x; f[i*4+1] = t.y; f[i*4+2] = t.z; f[i*4+3] = t.w;
        }
        u32 hw[8], lw[8];
        #pragma unroll
        for (int i = 0; i < 8; i++) {
            float a = f[2*i], b = f[2*i+1];
            __nv_bfloat16 h0 = __float2bfloat16(a), h1 = __float2bfloat16(b);
            hw[i] = packbf2(a, b);
            lw[i] = packbf2(a - __bfloat162float(h0), b - __bfloat162float(h1));
        }
        u32 bo = (u32)(r * 128 + cc * 32);
        sts128(dh + SWZ128(bo),      make_uint4(hw[0], hw[1], hw[2], hw[3]));
        sts128(dh + SWZ128(bo + 16), make_uint4(hw[4], hw[5], hw[6], hw[7]));
        sts128(dl + SWZ128(bo),      make_uint4(lw[0], lw[1], lw[2], lw[3]));
        sts128(dl + SWZ128(bo + 16), make_uint4(lw[4], lw[5], lw[6], lw[7]));
    }
}

// load V 128x64 fp32 -> transposed split smem vt[d][key], blocked atoms:
// block0 keys 0-63 at 0, block1 keys 64-127 at 8192. rows = d (128B each).
__device__ __forceinline__ void att_load_split_vt(
        u32 dh, u32 dl, const float* __restrict__ g, int tid) {
    int cc = tid & 3, r0 = tid >> 2;
    #pragma unroll
    for (int j = 0; j < 4; j++) {
        int r = r0 + j * 32;              // key index
        const float* src = g + (size_t)r * CD + cc * 16;
        float f[16];
        #pragma unroll
        for (int i = 0; i < 4; i++) {
            float4 t = *(const float4*)(src + i * 4);
            f[i*4] = t.x; f[i*4+1] = t.y; f[i*4+2] = t.z; f[i*4+3] = t.w;
        }
        u32 blk = (r >= 64) ? 8192u : 0u;
        u32 rr = (u32)(r & 63) * 2;
        #pragma unroll
        for (int i = 0; i < 16; i++) {
            int d = cc * 16 + i;
            __nv_bfloat16 hv = __float2bfloat16(f[i]);
            __nv_bfloat16 lv = __float2bfloat16(f[i] - __bfloat162float(hv));
            u32 off = blk + (u32)d * 128 + rr;
            STS16(dh + SWZ128(off), __bfloat16_as_ushort(hv));
            STS16(dl + SWZ128(off), __bfloat16_as_ushort(lv));
        }
    }
}
#endif

__global__ void __launch_bounds__(128, 2) attn_kernel() {
#if HAS_TCGEN05
    extern __shared__ char dsm[];
    u32 sb = (smem_u32(dsm) + 1023u) & ~1023u;
    const u32 TM_PTR = sb + ATT_CTRL;
    const u32 MB_S = TM_PTR + 8, MB_PV = TM_PTR + 16;

    int tid = threadIdx.x, wid = tid >> 5;
    int bh = blockIdx.x, b = bh >> 4, h = bh & 15;
    int qb = blockIdx.y;
    const size_t base = (size_t)b * NT * CD + h * HSD;
    const u32 woff = (u32)(wid << 21);

    if (wid == 0) {
        asm volatile("tcgen05.alloc.cta_group::1.sync.aligned.shared::cta.b32 [%0], %1;"
                     :: "r"(TM_PTR), "r"(256u) : "memory");
        asm volatile("tcgen05.relinquish_alloc_permit.cta_group::1.sync.aligned;");
    }
    if (tid == 0) { mbar_init(MB_S, 1); mbar_init(MB_PV, 1); }
    __syncthreads();
    u32 tmem;
    asm("ld.shared.b32 %0, [%1];" : "=r"(tmem) : "r"(TM_PTR));

    att_load_split(sb + ATT_QH, sb + ATT_QL,
                   g_q + base + (size_t)(qb * 128) * CD, tid);

    float m_i = -1e30f, l_i = 0.f;
    float o[64];
    #pragma unroll
    for (int d = 0; d < 64; d++) o[d] = 0.f;
    const float scale = 0.125f;
    u32 ph_s = 0, ph_pv = 0;

    for (int kb = 0; kb <= qb; kb++) {
        __syncthreads();
        att_load_split(sb + ATT_KH, sb + ATT_KL,
                       g_k + base + (size_t)(kb * 128) * CD, tid);
        att_load_split_vt(sb + ATT_VH, sb + ATT_VL,
                          g_v + base + (size_t)(kb * 128) * CD, tid);
        asm volatile("fence.proxy.async.shared::cta;" ::: "memory");
        __syncthreads();

        if (wid == 0 && elect1()) {
            u64 dqh = MKDESC128(sb + ATT_QH), dql = MKDESC128(sb + ATT_QL);
            u64 dkh = MKDESC128(sb + ATT_KH), dkl = MKDESC128(sb + ATT_KL);
            #pragma unroll
            for (int ks = 0; ks < 4; ks++) {
                mma_f16_ss(tmem, dqh + ks*2, dkh + ks*2, IDESC_128, ks == 0 ? 0u : 1u);
                mma_f16_ss(tmem, dqh + ks*2, dkl + ks*2, IDESC_128, 1u);
                mma_f16_ss(tmem, dql + ks*2, dkh + ks*2, IDESC_128, 1u);
            }
            asm volatile(
                "tcgen05.commit.cta_group::1.mbarrier::arrive::one.shared::cluster.b64 [%0];"
                :: "r"(MB_S) : "memory");
        }
        mbar_wait(MB_S, ph_s); ph_s ^= 1u;
        asm volatile("tcgen05.fence::after_thread_sync;" ::: "memory");

        u32 sr[128];
        LDTM32(sr +  0, tmem +  0);
        LDTM32(sr + 32, tmem + 32);
        LDTM32(sr + 64, tmem + 64);
        LDTM32(sr + 96, tmem + 96);
        asm volatile("tcgen05.wait::ld.sync.aligned;" ::: "memory");

        float tm = -1e30f;
        if (kb == qb) {
            #pragma unroll
            for (int j = 0; j < 128; j++) {
                float v = (j > tid) ? -1e30f : __uint_as_float(sr[j]) * scale;
                sr[j] = __float_as_uint(v);
                tm = fmaxf(tm, v);
            }
        } else {
            #pragma unroll
            for (int j = 0; j < 128; j++) {
                float v = __uint_as_float(sr[j]) * scale;
                sr[j] = __float_as_uint(v);
                tm = fmaxf(tm, v);
            }
        }
        float nm = fmaxf(m_i, tm);
        float corr = __expf(m_i - nm);

        float lsum = 0.f;
        #pragma unroll
        for (int c = 0; c < 8; c++) {
            u32 hw[8], lw[8];
            #pragma unroll
            for (int i = 0; i < 8; i++) {
                int j = c * 16 + i * 2;
                float e0 = __expf(__uint_as_float(sr[j])     - nm);
                float e1 = __expf(__uint_as_float(sr[j + 1]) - nm);
                lsum += e0 + e1;
                __nv_bfloat16 h0 = __float2bfloat16(e0), h1 = __float2bfloat16(e1);
                hw[i] = packbf2(e0, e1);
                lw[i] = packbf2(e0 - __bfloat162float(h0), e1 - __bfloat162float(h1));
            }
            STTM8(tmem + 128 + c * 8 + woff, hw);
            STTM8(tmem + 192 + c * 8 + woff, lw);
        }
        asm volatile("tcgen05.wait::st.sync.aligned;" ::: "memory");
        l_i = l_i * corr + lsum;
        m_i = nm;
        asm volatile("tcgen05.fence::before_thread_sync;" ::: "memory");
        __syncthreads();

        if (wid == 0 && elect1()) {
            asm volatile("tcgen05.fence::after_thread_sync;" ::: "memory");
            u64 dvh = MKDESC128(sb + ATT_VH), dvl = MKDESC128(sb + ATT_VL);
            #pragma unroll
            for (int ks = 0; ks < 8; ks++) {
                u64 off = (ks < 4) ? (u64)(ks * 2) : (u64)(512 + (ks - 4) * 2);
                u32 aph = tmem + 128 + ks * 8;
                u32 apl = tmem + 192 + ks * 8;
                mma_f16_ts(tmem, aph, dvh + off, IDESC_64, ks == 0 ? 0u : 1u);
                mma_f16_ts(tmem, aph, dvl + off, IDESC_64, 1u);
                mma_f16_ts(tmem, apl, dvh + off, IDESC_64, 1u);
            }
            asm volatile(
                "tcgen05.commit.cta_group::1.mbarrier::arrive::one.shared::cluster.b64 [%0];"
                :: "r"(MB_PV) : "memory");
        }
        mbar_wait(MB_PV, ph_pv); ph_pv ^= 1u;
        asm volatile("tcgen05.fence::after_thread_sync;" ::: "memory");

        u32 org[64];
        LDTM32(org,      tmem +  0);
        LDTM32(org + 32, tmem + 32);
        asm volatile("tcgen05.wait::ld.sync.aligned;" ::: "memory");
        #pragma unroll
        for (int d = 0; d < 64; d++)
            o[d] = o[d] * corr + __uint_as_float(org[d]);
    }

    {
        float inv = 1.f / l_i;
        size_t obase = ((size_t)(b * NT + qb * 128 + tid)) * CD + h * HSD;
        #pragma unroll
        for (int g4 = 0; g4 < 16; g4++) {
            write_split4(g_ah, g_al, obase + g4 * 4,
                         o[g4*4+0] * inv, o[g4*4+1] * inv,
                         o[g4*4+2] * inv, o[g4*4+3] * inv);
        }
    }
    __syncthreads();
    if (wid == 0) {
        asm volatile("tcgen05.dealloc.cta_group::1.sync.aligned.b32 %0, %1;"
                     :: "r"(tmem), "r"(256u));
    }
#else
    int tid = threadIdx.x;
    int bh = blockIdx.x, b = bh >> 4, h = bh & 15;
    int t = blockIdx.y * 128 + tid;
    const size_t base = (size_t)b * NT * CD + h * HSD;
    const float* q = &g_q[base + (size_t)t * CD];
    float m = -1e30f, l = 0.f, o[64];
    for (int d = 0; d < 64; d++) o[d] = 0.f;
    for (int key = 0; key <= t; key++) {
        const float* kk = &g_k[base + (size_t)key * CD];
        float s = 0.f;
        for (int d = 0; d < 64; d++) s += q[d] * kk[d];
        s *= 0.125f;
        float nm = fmaxf(m, s);
        float corr = __expf(m - nm), e = __expf(s - nm);
        l = l * corr + e; m = nm;
        const float* vv = &g_v[base + (size_t)key * CD];
        for (int d = 0; d < 64; d++) o[d] = o[d] * corr + e * vv[d];
    }
    float inv = 1.f / l;
    size_t obase = ((size_t)(b * NT + t)) * CD + h * HSD;
    for (int g4 = 0; g4 < 16; g4++)
        write_split4(g_ah, g_al, obase + g4 * 4,
                     o[g4*4+0]*inv, o[g4*4+1]*inv, o[g4*4+2]*inv, o[g4*4+3]*inv);
#endif
}

// ---------------- LM head (N=67) with fused final LayerNorm -----------------
__global__ void __launch_bounds__(128) lm_kernel(
        const float* __restrict__ W, const float* __restrict__ bias,
        const float* __restrict__ lg, const float* __restrict__ lb,
        float* __restrict__ out) {
    __shared__ float hs[CD];
    __shared__ float rs[4], rss[4];
    __shared__ float mean_s, rstd_s;
    int row = blockIdx.x;
    int tid = threadIdx.x;
    const float* x = g_x + (size_t)row * CD;
    float4 v0 = ((const float4*)x)[tid];
    float4 v1 = ((const float4*)x)[tid + 128];
    float s  = v0.x + v0.y + v0.z + v0.w + v1.x + v1.y + v1.z + v1.w;
    float ss = v0.x*v0.x + v0.y*v0.y + v0.z*v0.z + v0.w*v0.w
             + v1.x*v1.x + v1.y*v1.y + v1.z*v1.z + v1.w*v1.w;
    #pragma unroll
    for (int o = 16; o; o >>= 1) {
        s  += __shfl_xor_sync(0xffffffffu, s,  o);
        ss += __shfl_xor_sync(0xffffffffu, ss, o);
    }
    if ((tid & 31) == 0) { rs[tid >> 5] = s; rss[tid >> 5] = ss; }
    __syncthreads();
    if (tid == 0) {
        float S = rs[0] + rs[1] + rs[2] + rs[3];
        float SS = rss[0] + rss[1] + rss[2] + rss[3];
        float mean = S * (1.f / CD);
        float var  = SS * (1.f / CD) - mean * mean;
        mean_s = mean;
        rstd_s = rsqrtf(var + 1e-5f);
    }
    __syncthreads();
    float mean = mean_s, rstd = rstd_s;
    {
        float4 g0 = ((const float4*)lg)[tid];
        float4 b0 = ((const float4*)lb)[tid];
        float4 g1 = ((const float4*)lg)[tid + 128];
        float4 b1 = ((const float4*)lb)[tid + 128];
        float4 o0, o1;
        o0.x = (v0.x - mean) * rstd * g0.x + b0.x;
        o0.y = (v0.y - mean) * rstd * g0.y + b0.y;
        o0.z = (v0.z - mean) * rstd * g0.z + b0.z;
        o0.w = (v0.w - mean) * rstd * g0.w + b0.w;
        o1.x = (v1.x - mean) * rstd * g1.x + b1.x;
        o1.y = (v1.y - mean) * rstd * g1.y + b1.y;
        o1.z = (v1.z - mean) * rstd * g1.z + b1.z;
        o1.w = (v1.w - mean) * rstd * g1.w + b1.w;
        ((float4*)hs)[tid]       = o0;
        ((float4*)hs)[tid + 128] = o1;
    }
    __syncthreads();
    if (tid < NV) {
        float a0 = 0.f, a1 = 0.f, a2 = 0.f, a3 = 0.f;
        #pragma unroll 4
        for (int kk = 0; kk < CD; kk += 4) {
            a0 += hs[kk + 0] * W[(kk + 0) * NV + tid];
            a1 += hs[kk + 1] * W[(kk + 1) * NV + tid];
            a2 += hs[kk + 2] * W[(kk + 2) * NV + tid];
            a3 += hs[kk + 3] * W[(kk + 3) * NV + tid];
        }
        out[(size_t)row * NV + tid] = bias[tid] + ((a0 + a1) + (a2 + a3));
    }
}

// ------------------------- launch ------------------------------------------
static void split_layer(int l, cudaStream_t st,
                        const float* Wq, const float* Wk, const float* Wv,
                        const float* Wo, const float* W1, const float* W2) {
    dim3 wC(CD / 32, CD / 32);
    dim3 w1g(FFD / 32, CD / 32);
    dim3 w2g(CD / 32, FFD / 32);
    size_t p = (size_t)(l & 1) * WSEG;
    split_w_kernel<<<wC, 256, 0, st>>>(Wq + (size_t)l * CD * CD, CD, CD, p + WOFF_QKV);
    split_w_kernel<<<wC, 256, 0, st>>>(Wk + (size_t)l * CD * CD, CD, CD, p + WOFF_QKV + 1024 * 1024);
    split_w_kernel<<<wC, 256, 0, st>>>(Wv + (size_t)l * CD * CD, CD, CD, p + WOFF_QKV + 2 * 1024 * 1024);
    split_w_kernel<<<wC, 256, 0, st>>>(Wo + (size_t)l * CD * CD, CD, CD, p + WOFF_WO);
    split_w_kernel<<<w1g, 256, 0, st>>>(W1 + (size_t)l * CD * FFD, CD, FFD, p + WOFF_W1);
    split_w_kernel<<<w2g, 256, 0, st>>>(W2 + (size_t)l * FFD * CD, FFD, CD, p + WOFF_W2);
}

extern "C" void kernel_launch(void* const* d_in, const int* in_sizes, int n_in,
                              void* d_out, int out_size) {
    const int*   idx  = (const int*)  d_in[0];
    const float* tok  = (const float*)d_in[1];
    const float* pos  = (const float*)d_in[2];
    const float* Wq   = (const float*)d_in[3];
    const float* Wk   = (const float*)d_in[4];
    const float* Wv   = (const float*)d_in[5];
    const float* Wo   = (const float*)d_in[6];
    const float* bo   = (const float*)d_in[7];
    const float* ln1g = (const float*)d_in[8];
    const float* ln1b = (const float*)d_in[9];
    const float* ln2g = (const float*)d_in[10];
    const float* ln2b = (const float*)d_in[11];
    const float* W1   = (const float*)d_in[12];
    const float* b1   = (const float*)d_in[13];
    const float* W2   = (const float*)d_in[14];
    const float* b2   = (const float*)d_in[15];
    const float* lnfg = (const float*)d_in[16];
    const float* lnfb = (const float*)d_in[17];
    const float* Wlm  = (const float*)d_in[18];
    const float* blm  = (const float*)d_in[19];
    float* out = (float*)d_out;

    // side stream + events (host-side objects, created once; no device memory)
    static cudaStream_t s2 = nullptr;
    static cudaEvent_t evA[NL], evB[NL];
    if (!s2) {
        cudaStreamCreateWithFlags(&s2, cudaStreamNonBlocking);
        for (int i = 0; i < NL; i++) {
            cudaEventCreateWithFlags(&evA[i], cudaEventDisableTiming);
            cudaEventCreateWithFlags(&evB[i], cudaEventDisableTiming);
        }
    }

    cudaFuncSetAttribute(tcgemm_kernel<0>,
                         cudaFuncAttributeMaxDynamicSharedMemorySize, GEMM_SMEM);
    cudaFuncSetAttribute(tcgemm_kernel<1>,
                         cudaFuncAttributeMaxDynamicSharedMemorySize, GEMM_SMEM);
    cudaFuncSetAttribute(tcgemm_kernel<2>,
                         cudaFuncAttributeMaxDynamicSharedMemorySize, GEMM_SMEM);
    cudaFuncSetAttribute(tcgemm_kernel<3>,
                         cudaFuncAttributeMaxDynamicSharedMemorySize, GEMM_SMEM);
    cudaFuncSetAttribute(attn_kernel,
                         cudaFuncAttributeMaxDynamicSharedMemorySize, ATT_SMEM);

    dim3 gC(CD / BN, NM / BM);        // (4, 32)
    dim3 gQKV(3 * CD / BN, NM / BM);  // (12, 32)
    dim3 gF(FFD / BN, NM / BM);       // (16, 32)
    dim3 gA(NB * NH, NT / 128);       // (128, 8)
    dim3 wC(CD / 32, CD / 32);
    dim3 w1g(FFD / 32, CD / 32);
    dim3 w2g(CD / 32, FFD / 32);

    // ---- layer 0 (reordered so exec-order launch #6 = tcgemm<3> for ncu) ----
    embed_kernel<<<NM, 256>>>(idx, tok, pos);                                // 1
    split_w_kernel<<<wC, 256>>>(Wq, CD, CD, WOFF_QKV);                       // 2
    split_w_kernel<<<wC, 256>>>(Wk, CD, CD, WOFF_QKV + 1024 * 1024);         // 3
    split_w_kernel<<<wC, 256>>>(Wv, CD, CD, WOFF_QKV + 2 * 1024 * 1024);     // 4
    ln_kernel<<<NM, 256>>>(ln1g, ln1b);                                      // 5
    tcgemm_kernel<3><<<gQKV, 256, GEMM_SMEM>>>(
        nullptr, 0, 0, 0, 3 * CD, CD, WOFF_QKV);                             // 6
    // layer-0 Wo/W1/W2 splits: same stream, just moved after the QKV GEMM
    split_w_kernel<<<wC, 256>>>(Wo, CD, CD, WOFF_WO);
    split_w_kernel<<<w1g, 256>>>(W1, CD, FFD, WOFF_W1);
    split_w_kernel<<<w2g, 256>>>(W2, FFD, CD, WOFF_W2);
    // fork: prefetch layer 1 weights on side stream (join at end of layer 0)
    cudaEventRecord(evA[0], 0);
    cudaStreamWaitEvent(s2, evA[0], 0);
    split_layer(1, s2, Wq, Wk, Wv, Wo, W1, W2);
    cudaEventRecord(evB[0], s2);

    attn_kernel<<<gA, 128, ATT_SMEM>>>();
    tcgemm_kernel<1><<<gC, 256, GEMM_SMEM>>>(bo, 0, 0, 0, CD, CD, WOFF_WO);
    ln_kernel<<<NM, 256>>>(ln2g, ln2b);
    tcgemm_kernel<2><<<gF, 256, GEMM_SMEM>>>(b1, 0, 0, 0, FFD, CD, WOFF_W1);
    tcgemm_kernel<1><<<gC, 256, GEMM_SMEM>>>(b2, 1, 0, 0, CD, FFD, WOFF_W2);
    cudaStreamWaitEvent(0, evB[0], 0);   // layer-1 weights ready

    // ---- layers 1..NL-1 (identical to R15 schedule) ----
    for (int l = 1; l < NL; l++) {
        size_t p = (size_t)(l & 1) * WSEG;

        if (l + 1 < NL) {
            cudaEventRecord(evA[l], 0);
            cudaStreamWaitEvent(s2, evA[l], 0);
            split_layer(l + 1, s2, Wq, Wk, Wv, Wo, W1, W2);
            cudaEventRecord(evB[l], s2);
        }

        ln_kernel<<<NM, 256>>>(ln1g + (size_t)l * CD, ln1b + (size_t)l * CD);
        tcgemm_kernel<3><<<gQKV, 256, GEMM_SMEM>>>(
            nullptr, 0, 0, 0, 3 * CD, CD, p + WOFF_QKV);
        attn_kernel<<<gA, 128, ATT_SMEM>>>();
        tcgemm_kernel<1><<<gC, 256, GEMM_SMEM>>>(
            bo + (size_t)l * CD, 0, 0, 0, CD, CD, p + WOFF_WO);
        ln_kernel<<<NM, 256>>>(ln2g + (size_t)l * CD, ln2b + (size_t)l * CD);
        tcgemm_kernel<2><<<gF, 256, GEMM_SMEM>>>(
            b1 + (size_t)l * FFD, 0, 0, 0, FFD, CD, p + WOFF_W1);
        tcgemm_kernel<1><<<gC, 256, GEMM_SMEM>>>(
            b2 + (size_t)l * CD, 1, 0, 0, CD, FFD, p + WOFF_W2);

        if (l + 1 < NL) cudaStreamWaitEvent(0, evB[l], 0);
    }
    lm_kernel<<<NM, 128>>>(Wlm, blm, lnfg, lnfb, out);
}

// round 17
// speedup vs baseline: 1.3969x; 1.0135x over previous
#include <cuda_runtime.h>
#include <cuda_bf16.h>
#include <cstdint>
#include <cstddef>

#define NL 6
#define NH 16
#define CD 1024
#define HSD 64
#define FFD 4096
#define NV 67
#define NB 8
#define NT 1024
#define NM (NB*NT)   // 8192 rows

typedef unsigned long long u64;
typedef unsigned int u32;

// Arch-specific feature gate: tcgen05 only exists in the sm_103a cubin pass.
#if defined(__CUDA_ARCH__) && (defined(__CUDA_ARCH_FEAT_SM103_ALL) || defined(__CUDA_ARCH_SPECIFIC__))
#define HAS_TCGEN05 1
#else
#define HAS_TCGEN05 0
#endif

// weight segment layout (elements): QKV@0 (3M), Wo@3M (1M), W1@4M (4M), W2@8M (4M)
#define WSEG  12582912ull            // 12M elements per layer-parity segment
#define WOFF_QKV 0ull
#define WOFF_WO  3145728ull
#define WOFF_W1  4194304ull
#define WOFF_W2  8388608ull

// ------------------------- scratch (device globals, no allocation) ---------
__device__ float g_x [(size_t)NM*CD];
__device__ float g_h [(size_t)NM*CD];
__device__ float g_q [(size_t)NM*CD];
__device__ float g_k [(size_t)NM*CD];
__device__ float g_v [(size_t)NM*CD];
// bf16 split buffers: two activation pairs (ping/pong) + double-buffered weights
__device__ __nv_bfloat16 g_ah[(size_t)NM*FFD];
__device__ __nv_bfloat16 g_al[(size_t)NM*FFD];
__device__ __nv_bfloat16 g_bh[(size_t)NM*FFD];
__device__ __nv_bfloat16 g_bl[(size_t)NM*FFD];
__device__ __nv_bfloat16 g_wh[2*WSEG];
__device__ __nv_bfloat16 g_wl[2*WSEG];

__device__ __forceinline__ float* buf(int which) {
    switch (which) {
        case 0: return g_x;
        case 1: return g_h;
        case 2: return g_q;
        case 3: return g_k;
        default: return g_v;
    }
}

// ------------------------- PTX helpers -------------------------------------
__device__ __forceinline__ u32 smem_u32(const void* p) {
    u32 a;
    asm("{ .reg .u64 t; cvta.to.shared.u64 t, %1; cvt.u32.u64 %0, t; }"
        : "=r"(a) : "l"(p));
    return a;
}
#define SWZ64(o)  ((o) ^ (((o) >> 3) & 0x30))
#define SWZ128(o) ((o) ^ (((o) >> 3) & 0x70))

#define CP_ASYNC16(dst, src) \
    asm volatile("cp.async.cg.shared.global [%0], [%1], 16;" \
                 :: "r"(dst), "l"(src) : "memory")
#define CP_COMMIT() asm volatile("cp.async.commit_group;" ::: "memory")
#define CP_WAIT0()  asm volatile("cp.async.wait_group 0;" ::: "memory")
#define CP_WAIT1()  asm volatile("cp.async.wait_group 1;" ::: "memory")

#define STS16(addr, v) \
    asm volatile("st.shared.u16 [%0], %1;" :: "r"(addr), "h"(v) : "memory")

__device__ __forceinline__ void sts128(u32 addr, uint4 v) {
    asm volatile("st.shared.v4.b32 [%0], {%1,%2,%3,%4};"
                 :: "r"(addr), "r"(v.x), "r"(v.y), "r"(v.z), "r"(v.w) : "memory");
}

__device__ __forceinline__ u32 packbf2(float a, float b) {
    __nv_bfloat162 t(__float2bfloat16(a), __float2bfloat16(b));
    return *(u32*)&t;
}

__device__ __forceinline__ void mbar_init(u32 addr, u32 cnt) {
    asm volatile("mbarrier.init.shared.b64 [%0], %1;" :: "r"(addr), "r"(cnt) : "memory");
}
__device__ __forceinline__ void mbar_wait(u32 addr, u32 phase) {
    asm volatile("{\n\t.reg .pred P;\n\t"
        "W_%=:\n\t"
        "mbarrier.try_wait.parity.acquire.cta.shared::cta.b64 P, [%0], %1, 0x989680;\n\t"
        "@P bra.uni D_%=;\n\t"
        "bra.uni W_%=;\n\t"
        "D_%=:\n\t}"
        :: "r"(addr), "r"(phase) : "memory");
}

#if HAS_TCGEN05
__device__ __forceinline__ u32 elect1() {
    u32 pred;
    asm volatile("{\n\t.reg .pred p;\n\telect.sync _|p, 0xFFFFFFFF;\n\t"
                 "selp.b32 %0, 1, 0, p;\n\t}" : "=r"(pred));
    return pred;
}
__device__ __forceinline__ void mma_f16_ss(u32 d, u64 ad, u64 bd, u32 idesc, u32 acc) {
    asm volatile("{\n\t.reg .pred p;\n\tsetp.ne.u32 p, %5, 0;\n\t"
        "tcgen05.mma.cta_group::1.kind::f16 [%0], %1, %2, %3, {%4,%4,%4,%4}, p;\n\t}"
        :: "r"(d), "l"(ad), "l"(bd), "r"(idesc), "r"(0u), "r"(acc) : "memory");
}
__device__ __forceinline__ void mma_f16_ts(u32 d, u32 a, u64 bd, u32 idesc, u32 acc) {
    asm volatile("{\n\t.reg .pred p;\n\tsetp.ne.u32 p, %5, 0;\n\t"
        "tcgen05.mma.cta_group::1.kind::f16 [%0], [%1], %2, %3, {%4,%4,%4,%4}, p;\n\t}"
        :: "r"(d), "r"(a), "l"(bd), "r"(idesc), "r"(0u), "r"(acc) : "memory");
}
// SW64 desc (GEMM): layout=4, version=1, SBO=32, LBO=1
#define DESC64_BASE ((4ull<<61)|(1ull<<46)|(32ull<<32)|(1ull<<16))
#define MKDESC64(a) (DESC64_BASE | ((u64)((a) >> 4) & 0x3FFFull))
// SW128 desc (attention): layout=2, version=1, SBO=64, LBO=1
#define DESC128_BASE ((2ull<<61)|(1ull<<46)|(64ull<<32)|(1ull<<16))
#define MKDESC128(a) (DESC128_BASE | ((u64)((a) >> 4) & 0x3FFFull))
#define IDESC_256 0x8400490u   // F32 acc, BF16xBF16, M=128, N=256
#define IDESC_128 0x8200490u   // M=128, N=128
#define IDESC_64  0x8100490u   // M=128, N=64

#define LDTM32(r, ta) \
    asm volatile("tcgen05.ld.sync.aligned.32x32b.x32.b32 " \
        "{%0,%1,%2,%3,%4,%5,%6,%7,%8,%9,%10,%11,%12,%13,%14,%15," \
        "%16,%17,%18,%19,%20,%21,%22,%23,%24,%25,%26,%27,%28,%29,%30,%31}, [%32];" \
        : "=r"((r)[0]),"=r"((r)[1]),"=r"((r)[2]),"=r"((r)[3]), \
          "=r"((r)[4]),"=r"((r)[5]),"=r"((r)[6]),"=r"((r)[7]), \
          "=r"((r)[8]),"=r"((r)[9]),"=r"((r)[10]),"=r"((r)[11]), \
          "=r"((r)[12]),"=r"((r)[13]),"=r"((r)[14]),"=r"((r)[15]), \
          "=r"((r)[16]),"=r"((r)[17]),"=r"((r)[18]),"=r"((r)[19]), \
          "=r"((r)[20]),"=r"((r)[21]),"=r"((r)[22]),"=r"((r)[23]), \
          "=r"((r)[24]),"=r"((r)[25]),"=r"((r)[26]),"=r"((r)[27]), \
          "=r"((r)[28]),"=r"((r)[29]),"=r"((r)[30]),"=r"((r)[31]) \
        : "r"(ta))

#define STTM8(ta, r) \
    asm volatile("tcgen05.st.sync.aligned.32x32b.x8.b32 [%0], " \
        "{%1,%2,%3,%4,%5,%6,%7,%8};" \
        :: "r"(ta), "r"((r)[0]), "r"((r)[1]), "r"((r)[2]), "r"((r)[3]), \
           "r"((r)[4]), "r"((r)[5]), "r"((r)[6]), "r"((r)[7]) : "memory")
#endif

// ------------------------- embedding ---------------------------------------
__global__ void __launch_bounds__(256) embed_kernel(
        const int* __restrict__ idx, const float* __restrict__ tok,
        const float* __restrict__ pos) {
    int row = blockIdx.x;
    int t = row & (NT - 1);
    int token = idx[row];
    const float4* t4 = (const float4*)(tok + (size_t)token * CD);
    const float4* p4 = (const float4*)(pos + (size_t)t * CD);
    float4 a = t4[threadIdx.x];
    float4 b = p4[threadIdx.x];
    a.x += b.x; a.y += b.y; a.z += b.z; a.w += b.w;
    ((float4*)(g_x + (size_t)row * CD))[threadIdx.x] = a;
}

// ------------------------- split write helper -------------------------------
__device__ __forceinline__ void write_split4(
        __nv_bfloat16* __restrict__ ph, __nv_bfloat16* __restrict__ pl,
        size_t o, float a0, float a1, float a2, float a3) {
    __nv_bfloat16 h0 = __float2bfloat16(a0), h1 = __float2bfloat16(a1);
    __nv_bfloat16 h2 = __float2bfloat16(a2), h3 = __float2bfloat16(a3);
    *(__nv_bfloat162*)&ph[o]     = __nv_bfloat162(h0, h1);
    *(__nv_bfloat162*)&ph[o + 2] = __nv_bfloat162(h2, h3);
    *(__nv_bfloat162*)&pl[o] = __nv_bfloat162(
        __float2bfloat16(a0 - __bfloat162float(h0)),
        __float2bfloat16(a1 - __bfloat162float(h1)));
    *(__nv_bfloat162*)&pl[o + 2] = __nv_bfloat162(
        __float2bfloat16(a2 - __bfloat162float(h2)),
        __float2bfloat16(a3 - __bfloat162float(h3)));
}

// ------------------------- layernorm (fused split) --------------------------
__global__ void __launch_bounds__(256) ln_kernel(
        const float* __restrict__ g, const float* __restrict__ b) {
    __shared__ float rs[8], rss[8];
    __shared__ float mean_s, rstd_s;
    const float* x = g_x;
    int row = blockIdx.x, tid = threadIdx.x;
    float4 v = ((const float4*)(x + (size_t)row * CD))[tid];
    float s  = v.x + v.y + v.z + v.w;
    float ss = v.x*v.x + v.y*v.y + v.z*v.z + v.w*v.w;
    #pragma unroll
    for (int o = 16; o; o >>= 1) {
        s  += __shfl_xor_sync(0xffffffffu, s,  o);
        ss += __shfl_xor_sync(0xffffffffu, ss, o);
    }
    if ((tid & 31) == 0) { rs[tid >> 5] = s; rss[tid >> 5] = ss; }
    __syncthreads();
    if (tid == 0) {
        float S = 0.f, SS = 0.f;
        #pragma unroll
        for (int i = 0; i < 8; i++) { S += rs[i]; SS += rss[i]; }
        float mean = S * (1.f / CD);
        float var  = SS * (1.f / CD) - mean * mean;
        mean_s = mean;
        rstd_s = rsqrtf(var + 1e-5f);
    }
    __syncthreads();
    float mean = mean_s, rstd = rstd_s;
    float4 gg = ((const float4*)g)[tid];
    float4 bb = ((const float4*)b)[tid];
    float o0 = (v.x - mean) * rstd * gg.x + bb.x;
    float o1 = (v.y - mean) * rstd * gg.y + bb.y;
    float o2 = (v.z - mean) * rstd * gg.z + bb.z;
    float o3 = (v.w - mean) * rstd * gg.w + bb.w;
    write_split4(g_ah, g_al, (size_t)row * CD + tid * 4, o0, o1, o2, o3);
}

// W[K,N] fp32 -> g_wh/g_wl at element offset woff, [N,K] bf16 (transposed)
__global__ void __launch_bounds__(256) split_w_kernel(
        const float* __restrict__ W, int K, int N, size_t woff) {
    __shared__ float t[32][33];
    int n0 = blockIdx.x * 32, k0 = blockIdx.y * 32;
    int tx = threadIdx.x & 31, ty = threadIdx.x >> 5;
    #pragma unroll
    for (int i = 0; i < 4; i++)
        t[ty + i * 8][tx] = W[(size_t)(k0 + ty + i * 8) * N + n0 + tx];
    __syncthreads();
    #pragma unroll
    for (int i = 0; i < 4; i++) {
        int n = ty + i * 8;
        float a = t[tx][n];
        __nv_bfloat16 hi = __float2bfloat16(a);
        float lo = a - __bfloat162float(hi);
        size_t o = woff + (size_t)(n0 + n) * K + k0 + tx;
        g_wh[o] = hi;
        g_wl[o] = __float2bfloat16(lo);
    }
}

// --------- bf16-split GEMM (256x256, BK=32, 3-stage cp.async) ---------------
#define BM 256
#define BN 256
#define BK 32
#define OFF_AH 0
#define OFF_AL 16384
#define OFF_BH 32768
#define OFF_BL 49152
#define STAGE  65536
#define NSTG   3
#define GEMM_SMEM (NSTG*STAGE + 2048)

__device__ __forceinline__ void load_stage_async(
        u32 stg, const __nv_bfloat16* __restrict__ ah,
        const __nv_bfloat16* __restrict__ al,
        const __nv_bfloat16* __restrict__ bh,
        const __nv_bfloat16* __restrict__ bl,
        int m0, int n0, int k0, int K, int tid) {
    int cc = tid & 3;
    int r0 = tid >> 2;
    #pragma unroll
    for (int j = 0; j < 4; j++) {
        int r = r0 + j * 64;
        u32 so = SWZ64((u32)(r * 64 + cc * 16));
        size_t aoff = (size_t)(m0 + r) * K + k0 + cc * 8;
        size_t boff = (size_t)(n0 + r) * K + k0 + cc * 8;
        CP_ASYNC16(stg + OFF_AH + so, (const void*)(ah + aoff));
        CP_ASYNC16(stg + OFF_AL + so, (const void*)(al + aoff));
        CP_ASYNC16(stg + OFF_BH + so, (const void*)(bh + boff));
        CP_ASYNC16(stg + OFF_BL + so, (const void*)(bl + boff));
    }
}

// EP=0: fp32 out. EP=1: +bias +res, fp32 out.
// EP=2: +bias, relu, split out to g_bh/g_bl. EP=3: QKV demux to g_q/g_k/g_v.
template<int EP>
__device__ __forceinline__ void ep_write4(
        float c0, float c1, float c2, float c3,
        const float* __restrict__ bias, const float* __restrict__ res,
        float* __restrict__ out, size_t m, int n, int N) {
    if (EP == 1 || EP == 2) {
        float4 bv = *(const float4*)&bias[n];
        c0 += bv.x; c1 += bv.y; c2 += bv.z; c3 += bv.w;
    }
    if (EP == 1) {
        float4 rv = *(const float4*)&res[m * N + n];
        c0 += rv.x; c1 += rv.y; c2 += rv.z; c3 += rv.w;
        *(float4*)&out[m * N + n] = make_float4(c0, c1, c2, c3);
    } else if (EP == 2) {
        c0 = fmaxf(c0, 0.f); c1 = fmaxf(c1, 0.f);
        c2 = fmaxf(c2, 0.f); c3 = fmaxf(c3, 0.f);
        write_split4(g_bh, g_bl, m * N + n, c0, c1, c2, c3);
    } else if (EP == 3) {
        int which = n >> 10;
        float* o = (which == 0) ? g_q : (which == 1) ? g_k : g_v;
        *(float4*)&o[m * CD + (n & 1023)] = make_float4(c0, c1, c2, c3);
    } else {
        *(float4*)&out[m * N + n] = make_float4(c0, c1, c2, c3);
    }
}

template<int EP>
__global__ void __launch_bounds__(256, 1) tcgemm_kernel(
        const float* __restrict__ bias, int asel, int rsel, int osel,
        int N, int K, size_t woff) {
    extern __shared__ char dsm[];
    u32 sb = (smem_u32(dsm) + 1023u) & ~1023u;
    int tid = threadIdx.x, wid = tid >> 5, lid = tid & 31;
    int m0 = blockIdx.y * BM, n0 = blockIdx.x * BN;
    const int NS = K / BK;
    const float* res = buf(rsel);
    float* out = buf(osel);
    const __nv_bfloat16* Ah = asel ? g_bh : g_ah;
    const __nv_bfloat16* Al = asel ? g_bl : g_al;
    const __nv_bfloat16* Bh = g_wh + woff;
    const __nv_bfloat16* Bl = g_wl + woff;

#if HAS_TCGEN05
    const u32 TM_PTR = sb + NSTG * STAGE;
    u32 mb[3] = {TM_PTR + 8, TM_PTR + 16, TM_PTR + 24};

    if (wid == 0) {
        asm volatile("tcgen05.alloc.cta_group::1.sync.aligned.shared::cta.b32 [%0], %1;"
                     :: "r"(TM_PTR), "r"(512u) : "memory");
        asm volatile("tcgen05.relinquish_alloc_permit.cta_group::1.sync.aligned;");
    }
    if (tid == 0) {
        mbar_init(mb[0], 1); mbar_init(mb[1], 1); mbar_init(mb[2], 1);
    }
    __syncthreads();
    u32 tmem;
    asm("ld.shared.b32 %0, [%1];" : "=r"(tmem) : "r"(TM_PTR));

    load_stage_async(sb, Ah, Al, Bh, Bl, m0, n0, 0, K, tid);
    CP_COMMIT();
    load_stage_async(sb + STAGE, Ah, Al, Bh, Bl, m0, n0, BK, K, tid);
    CP_COMMIT();

    u32 phx[3] = {0, 0, 0};
    for (int s = 0; s < NS; s++) {
        int b = s - (s / 3) * 3;
        u32 stg = sb + b * STAGE;
        if (s + 1 < NS) CP_WAIT1();
        else            CP_WAIT0();
        __syncthreads();
        if (wid == 0) {
            asm volatile("fence.proxy.async.shared::cta;" ::: "memory");
            if (elect1()) {
                u64 dah = MKDESC64(stg + OFF_AH);
                u64 dal = MKDESC64(stg + OFF_AL);
                u64 dbh = MKDESC64(stg + OFF_BH);
                u64 dbl = MKDESC64(stg + OFF_BL);
                #pragma unroll
                for (int half = 0; half < 2; half++) {
                    u32 d = tmem + half * 256;
                    u64 ha = dah + half * 512;   // +8192B = rows 128..255
                    u64 la = dal + half * 512;
                    #pragma unroll
                    for (int kk = 0; kk < 2; kk++) {
                        mma_f16_ss(d, ha + kk * 2, dbh + kk * 2, IDESC_256,
                                   (s == 0 && kk == 0) ? 0u : 1u);
                        mma_f16_ss(d, ha + kk * 2, dbl + kk * 2, IDESC_256, 1u);
                        mma_f16_ss(d, la + kk * 2, dbh + kk * 2, IDESC_256, 1u);
                    }
                }
                asm volatile(
                    "tcgen05.commit.cta_group::1.mbarrier::arrive::one.shared::cluster.b64 [%0];"
                    :: "r"(mb[b]) : "memory");
            }
        }
        if (s + 2 < NS) {
            int nb = (s + 2) - ((s + 2) / 3) * 3;
            if (s >= 1) { mbar_wait(mb[nb], phx[nb]); phx[nb] ^= 1u; }
            load_stage_async(sb + nb * STAGE, Ah, Al, Bh, Bl, m0, n0,
                             (s + 2) * BK, K, tid);
            CP_COMMIT();
        }
    }
    {
        int fb = (NS - 1) - ((NS - 1) / 3) * 3;
        mbar_wait(mb[fb], phx[fb]);
    }
    asm volatile("tcgen05.fence::after_thread_sync;" ::: "memory");

    {
        int half = wid >> 2, w4 = wid & 3;
        size_t m = (size_t)m0 + half * 128 + w4 * 32 + lid;
        u32 tbase = tmem + half * 256;
        for (int c0 = 0; c0 < BN; c0 += 32) {
            u32 r[32];
            LDTM32(r, tbase + c0);
            asm volatile("tcgen05.wait::ld.sync.aligned;" ::: "memory");
            #pragma unroll
            for (int q = 0; q < 8; q++) {
                int n = n0 + c0 + q * 4;
                ep_write4<EP>(__uint_as_float(r[q*4+0]), __uint_as_float(r[q*4+1]),
                              __uint_as_float(r[q*4+2]), __uint_as_float(r[q*4+3]),
                              bias, res, out, m, n, N);
            }
        }
    }
    __syncthreads();
    if (wid == 0) {
        asm volatile("tcgen05.dealloc.cta_group::1.sync.aligned.b32 %0, %1;"
                     :: "r"(tmem), "r"(512u));
    }
#else
    // Base-PTX fallback: never selected at runtime (sm_103a cubin exists).
    (void)sb; (void)lid; (void)wid;
    int r = tid;
    for (int jn4 = 0; jn4 < BN; jn4 += 4) {
        float c[4];
        #pragma unroll
        for (int jj = 0; jj < 4; jj++) {
            int n = n0 + jn4 + jj;
            float acc = 0.f;
            const __nv_bfloat16* ah = Ah + (size_t)(m0 + r) * K;
            const __nv_bfloat16* al = Al + (size_t)(m0 + r) * K;
            const __nv_bfloat16* bh = Bh + (size_t)n * K;
            const __nv_bfloat16* bl = Bl + (size_t)n * K;
            for (int k = 0; k < K; k++) {
                float av = __bfloat162float(ah[k]) + __bfloat162float(al[k]);
                float bv = __bfloat162float(bh[k]) + __bfloat162float(bl[k]);
                acc += av * bv;
            }
            c[jj] = acc;
        }
        ep_write4<EP>(c[0], c[1], c[2], c[3], bias, res, out,
                      (size_t)(m0 + r), n0 + jn4, N);
    }
#endif
}

// ------------------------- tensor-core flash attention ----------------------
#define ATT_QH 0
#define ATT_QL 16384
#define ATT_KH 32768
#define ATT_KL 49152
#define ATT_VH 65536
#define ATT_VL 81920
#define ATT_CTRL 98304
#define ATT_SMEM (98304 + 64)

#if HAS_TCGEN05
// load a 128x64 fp32 tile (row stride CD) -> split bf16 smem, SW128 rows of 128B
__device__ __forceinline__ void att_load_split(
        u32 dh, u32 dl, const float* __restrict__ g, int tid) {
    int cc = tid & 3, r0 = tid >> 2;
    #pragma unroll
    for (int j = 0; j < 4; j++) {
        int r = r0 + j * 32;
        const float* src = g + (size_t)r * CD + cc * 16;
        float f[16];
        #pragma unroll
        for (int i = 0; i < 4; i++) {
            float4 t = *(const float4*)(src + i * 4);
            f[i*4] = t.x; f[i*4+1] = t.y; f[i*4+2] = t.z; f[i*4+3] = t.w;
        }
        u32 hw[8], lw[8];
        #pragma unroll
        for (int i = 0; i < 8; i++) {
            float a = f[2*i], b = f[2*i+1];
            __nv_bfloat16 h0 = __float2bfloat16(a), h1 = __float2bfloat16(b);
            hw[i] = packbf2(a, b);
            lw[i] = packbf2(a - __bfloat162float(h0), b - __bfloat162float(h1));
        }
        u32 bo = (u32)(r * 128 + cc * 32);
        sts128(dh + SWZ128(bo),      make_uint4(hw[0], hw[1], hw[2], hw[3]));
        sts128(dh + SWZ128(bo + 16), make_uint4(hw[4], hw[5], hw[6], hw[7]));
        sts128(dl + SWZ128(bo),      make_uint4(lw[0], lw[1], lw[2], lw[3]));
        sts128(dl + SWZ128(bo + 16), make_uint4(lw[4], lw[5], lw[6], lw[7]));
    }
}

// load V 128x64 fp32 -> transposed split smem vt[d][key], blocked atoms:
// block0 keys 0-63 at 0, block1 keys 64-127 at 8192. rows = d (128B each).
__device__ __forceinline__ void att_load_split_vt(
        u32 dh, u32 dl, const float* __restrict__ g, int tid) {
    int cc = tid & 3, r0 = tid >> 2;
    #pragma unroll
    for (int j = 0; j < 4; j++) {
        int r = r0 + j * 32;              // key index
        const float* src = g + (size_t)r * CD + cc * 16;
        float f[16];
        #pragma unroll
        for (int i = 0; i < 4; i++) {
            float4 t = *(const float4*)(src + i * 4);
            f[i*4] = t.x; f[i*4+1] = t.y; f[i*4+2] = t.z; f[i*4+3] = t.w;
        }
        u32 blk = (r >= 64) ? 8192u : 0u;
        u32 rr = (u32)(r & 63) * 2;
        #pragma unroll
        for (int i = 0; i < 16; i++) {
            int d = cc * 16 + i;
            __nv_bfloat16 hv = __float2bfloat16(f[i]);
            __nv_bfloat16 lv = __float2bfloat16(f[i] - __bfloat162float(hv));
            u32 off = blk + (u32)d * 128 + rr;
            STS16(dh + SWZ128(off), __bfloat16_as_ushort(hv));
            STS16(dl + SWZ128(off), __bfloat16_as_ushort(lv));
        }
    }
}
#endif

__global__ void __launch_bounds__(128, 2) attn_kernel() {
#if HAS_TCGEN05
    extern __shared__ char dsm[];
    u32 sb = (smem_u32(dsm) + 1023u) & ~1023u;
    const u32 TM_PTR = sb + ATT_CTRL;
    const u32 MB_S = TM_PTR + 8, MB_PV = TM_PTR + 16;

    int tid = threadIdx.x, wid = tid >> 5;
    int bh = blockIdx.x, b = bh >> 4, h = bh & 15;
    // LPT scheduling: longest CTAs (largest qb) get the smallest linear block
    // index so they start in the first wave; short CTAs backfill the tail.
    int qb = (gridDim.y - 1) - blockIdx.y;
    const size_t base = (size_t)b * NT * CD + h * HSD;
    const u32 woff = (u32)(wid << 21);

    if (wid == 0) {
        asm volatile("tcgen05.alloc.cta_group::1.sync.aligned.shared::cta.b32 [%0], %1;"
                     :: "r"(TM_PTR), "r"(256u) : "memory");
        asm volatile("tcgen05.relinquish_alloc_permit.cta_group::1.sync.aligned;");
    }
    if (tid == 0) { mbar_init(MB_S, 1); mbar_init(MB_PV, 1); }
    __syncthreads();
    u32 tmem;
    asm("ld.shared.b32 %0, [%1];" : "=r"(tmem) : "r"(TM_PTR));

    att_load_split(sb + ATT_QH, sb + ATT_QL,
                   g_q + base + (size_t)(qb * 128) * CD, tid);

    float m_i = -1e30f, l_i = 0.f;
    float o[64];
    #pragma unroll
    for (int d = 0; d < 64; d++) o[d] = 0.f;
    const float scale = 0.125f;
    u32 ph_s = 0, ph_pv = 0;

    for (int kb = 0; kb <= qb; kb++) {
        __syncthreads();
        att_load_split(sb + ATT_KH, sb + ATT_KL,
                       g_k + base + (size_t)(kb * 128) * CD, tid);
        att_load_split_vt(sb + ATT_VH, sb + ATT_VL,
                          g_v + base + (size_t)(kb * 128) * CD, tid);
        asm volatile("fence.proxy.async.shared::cta;" ::: "memory");
        __syncthreads();

        if (wid == 0 && elect1()) {
            u64 dqh = MKDESC128(sb + ATT_QH), dql = MKDESC128(sb + ATT_QL);
            u64 dkh = MKDESC128(sb + ATT_KH), dkl = MKDESC128(sb + ATT_KL);
            #pragma unroll
            for (int ks = 0; ks < 4; ks++) {
                mma_f16_ss(tmem, dqh + ks*2, dkh + ks*2, IDESC_128, ks == 0 ? 0u : 1u);
                mma_f16_ss(tmem, dqh + ks*2, dkl + ks*2, IDESC_128, 1u);
                mma_f16_ss(tmem, dql + ks*2, dkh + ks*2, IDESC_128, 1u);
            }
            asm volatile(
                "tcgen05.commit.cta_group::1.mbarrier::arrive::one.shared::cluster.b64 [%0];"
                :: "r"(MB_S) : "memory");
        }
        mbar_wait(MB_S, ph_s); ph_s ^= 1u;
        asm volatile("tcgen05.fence::after_thread_sync;" ::: "memory");

        u32 sr[128];
        LDTM32(sr +  0, tmem +  0);
        LDTM32(sr + 32, tmem + 32);
        LDTM32(sr + 64, tmem + 64);
        LDTM32(sr + 96, tmem + 96);
        asm volatile("tcgen05.wait::ld.sync.aligned;" ::: "memory");

        float tm = -1e30f;
        if (kb == qb) {
            #pragma unroll
            for (int j = 0; j < 128; j++) {
                float v = (j > tid) ? -1e30f : __uint_as_float(sr[j]) * scale;
                sr[j] = __float_as_uint(v);
                tm = fmaxf(tm, v);
            }
        } else {
            #pragma unroll
            for (int j = 0; j < 128; j++) {
                float v = __uint_as_float(sr[j]) * scale;
                sr[j] = __float_as_uint(v);
                tm = fmaxf(tm, v);
            }
        }
        float nm = fmaxf(m_i, tm);
        float corr = __expf(m_i - nm);

        float lsum = 0.f;
        #pragma unroll
        for (int c = 0; c < 8; c++) {
            u32 hw[8], lw[8];
            #pragma unroll
            for (int i = 0; i < 8; i++) {
                int j = c * 16 + i * 2;
                float e0 = __expf(__uint_as_float(sr[j])     - nm);
                float e1 = __expf(__uint_as_float(sr[j + 1]) - nm);
                lsum += e0 + e1;
                __nv_bfloat16 h0 = __float2bfloat16(e0), h1 = __float2bfloat16(e1);
                hw[i] = packbf2(e0, e1);
                lw[i] = packbf2(e0 - __bfloat162float(h0), e1 - __bfloat162float(h1));
            }
            STTM8(tmem + 128 + c * 8 + woff, hw);
            STTM8(tmem + 192 + c * 8 + woff, lw);
        }
        asm volatile("tcgen05.wait::st.sync.aligned;" ::: "memory");
        l_i = l_i * corr + lsum;
        m_i = nm;
        asm volatile("tcgen05.fence::before_thread_sync;" ::: "memory");
        __syncthreads();

        if (wid == 0 && elect1()) {
            asm volatile("tcgen05.fence::after_thread_sync;" ::: "memory");
            u64 dvh = MKDESC128(sb + ATT_VH), dvl = MKDESC128(sb + ATT_VL);
            #pragma unroll
            for (int ks = 0; ks < 8; ks++) {
                u64 off = (ks < 4) ? (u64)(ks * 2) : (u64)(512 + (ks - 4) * 2);
                u32 aph = tmem + 128 + ks * 8;
                u32 apl = tmem + 192 + ks * 8;
                mma_f16_ts(tmem, aph, dvh + off, IDESC_64, ks == 0 ? 0u : 1u);
                mma_f16_ts(tmem, aph, dvl + off, IDESC_64, 1u);
                mma_f16_ts(tmem, apl, dvh + off, IDESC_64, 1u);
            }
            asm volatile(
                "tcgen05.commit.cta_group::1.mbarrier::arrive::one.shared::cluster.b64 [%0];"
                :: "r"(MB_PV) : "memory");
        }
        mbar_wait(MB_PV, ph_pv); ph_pv ^= 1u;
        asm volatile("tcgen05.fence::after_thread_sync;" ::: "memory");

        u32 org[64];
        LDTM32(org,      tmem +  0);
        LDTM32(org + 32, tmem + 32);
        asm volatile("tcgen05.wait::ld.sync.aligned;" ::: "memory");
        #pragma unroll
        for (int d = 0; d < 64; d++)
            o[d] = o[d] * corr + __uint_as_float(org[d]);
    }

    {
        float inv = 1.f / l_i;
        size_t obase = ((size_t)(b * NT + qb * 128 + tid)) * CD + h * HSD;
        #pragma unroll
        for (int g4 = 0; g4 < 16; g4++) {
            write_split4(g_ah, g_al, obase + g4 * 4,
                         o[g4*4+0] * inv, o[g4*4+1] * inv,
                         o[g4*4+2] * inv, o[g4*4+3] * inv);
        }
    }
    __syncthreads();
    if (wid == 0) {
        asm volatile("tcgen05.dealloc.cta_group::1.sync.aligned.b32 %0, %1;"
                     :: "r"(tmem), "r"(256u));
    }
#else
    int tid = threadIdx.x;
    int bh = blockIdx.x, b = bh >> 4, h = bh & 15;
    int qb = (gridDim.y - 1) - blockIdx.y;
    int t = qb * 128 + tid;
    const size_t base = (size_t)b * NT * CD + h * HSD;
    const float* q = &g_q[base + (size_t)t * CD];
    float m = -1e30f, l = 0.f, o[64];
    for (int d = 0; d < 64; d++) o[d] = 0.f;
    for (int key = 0; key <= t; key++) {
        const float* kk = &g_k[base + (size_t)key * CD];
        float s = 0.f;
        for (int d = 0; d < 64; d++) s += q[d] * kk[d];
        s *= 0.125f;
        float nm = fmaxf(m, s);
        float corr = __expf(m - nm), e = __expf(s - nm);
        l = l * corr + e; m = nm;
        const float* vv = &g_v[base + (size_t)key * CD];
        for (int d = 0; d < 64; d++) o[d] = o[d] * corr + e * vv[d];
    }
    float inv = 1.f / l;
    size_t obase = ((size_t)(b * NT + t)) * CD + h * HSD;
    for (int g4 = 0; g4 < 16; g4++)
        write_split4(g_ah, g_al, obase + g4 * 4,
                     o[g4*4+0]*inv, o[g4*4+1]*inv, o[g4*4+2]*inv, o[g4*4+3]*inv);
#endif
}

// ---------------- LM head (N=67) with fused final LayerNorm -----------------
__global__ void __launch_bounds__(128) lm_kernel(
        const float* __restrict__ W, const float* __restrict__ bias,
        const float* __restrict__ lg, const float* __restrict__ lb,
        float* __restrict__ out) {
    __shared__ float hs[CD];
    __shared__ float rs[4], rss[4];
    __shared__ float mean_s, rstd_s;
    int row = blockIdx.x;
    int tid = threadIdx.x;
    const float* x = g_x + (size_t)row * CD;
    float4 v0 = ((const float4*)x)[tid];
    float4 v1 = ((const float4*)x)[tid + 128];
    float s  = v0.x + v0.y + v0.z + v0.w + v1.x + v1.y + v1.z + v1.w;
    float ss = v0.x*v0.x + v0.y*v0.y + v0.z*v0.z + v0.w*v0.w
             + v1.x*v1.x + v1.y*v1.y + v1.z*v1.z + v1.w*v1.w;
    #pragma unroll
    for (int o = 16; o; o >>= 1) {
        s  += __shfl_xor_sync(0xffffffffu, s,  o);
        ss += __shfl_xor_sync(0xffffffffu, ss, o);
    }
    if ((tid & 31) == 0) { rs[tid >> 5] = s; rss[tid >> 5] = ss; }
    __syncthreads();
    if (tid == 0) {
        float S = rs[0] + rs[1] + rs[2] + rs[3];
        float SS = rss[0] + rss[1] + rss[2] + rss[3];
        float mean = S * (1.f / CD);
        float var  = SS * (1.f / CD) - mean * mean;
        mean_s = mean;
        rstd_s = rsqrtf(var + 1e-5f);
    }
    __syncthreads();
    float mean = mean_s, rstd = rstd_s;
    {
        float4 g0 = ((const float4*)lg)[tid];
        float4 b0 = ((const float4*)lb)[tid];
        float4 g1 = ((const float4*)lg)[tid + 128];
        float4 b1 = ((const float4*)lb)[tid + 128];
        float4 o0, o1;
        o0.x = (v0.x - mean) * rstd * g0.x + b0.x;
        o0.y = (v0.y - mean) * rstd * g0.y + b0.y;
        o0.z = (v0.z - mean) * rstd * g0.z + b0.z;
        o0.w = (v0.w - mean) * rstd * g0.w + b0.w;
        o1.x = (v1.x - mean) * rstd * g1.x + b1.x;
        o1.y = (v1.y - mean) * rstd * g1.y + b1.y;
        o1.z = (v1.z - mean) * rstd * g1.z + b1.z;
        o1.w = (v1.w - mean) * rstd * g1.w + b1.w;
        ((float4*)hs)[tid]       = o0;
        ((float4*)hs)[tid + 128] = o1;
    }
    __syncthreads();
    if (tid < NV) {
        float a0 = 0.f, a1 = 0.f, a2 = 0.f, a3 = 0.f;
        #pragma unroll 4
        for (int kk = 0; kk < CD; kk += 4) {
            a0 += hs[kk + 0] * W[(kk + 0) * NV + tid];
            a1 += hs[kk + 1] * W[(kk + 1) * NV + tid];
            a2 += hs[kk + 2] * W[(kk + 2) * NV + tid];
            a3 += hs[kk + 3] * W[(kk + 3) * NV + tid];
        }
        out[(size_t)row * NV + tid] = bias[tid] + ((a0 + a1) + (a2 + a3));
    }
}

// ------------------------- launch ------------------------------------------
static void split_layer(int l, cudaStream_t st,
                        const float* Wq, const float* Wk, const float* Wv,
                        const float* Wo, const float* W1, const float* W2) {
    dim3 wC(CD / 32, CD / 32);
    dim3 w1g(FFD / 32, CD / 32);
    dim3 w2g(CD / 32, FFD / 32);
    size_t p = (size_t)(l & 1) * WSEG;
    split_w_kernel<<<wC, 256, 0, st>>>(Wq + (size_t)l * CD * CD, CD, CD, p + WOFF_QKV);
    split_w_kernel<<<wC, 256, 0, st>>>(Wk + (size_t)l * CD * CD, CD, CD, p + WOFF_QKV + 1024 * 1024);
    split_w_kernel<<<wC, 256, 0, st>>>(Wv + (size_t)l * CD * CD, CD, CD, p + WOFF_QKV + 2 * 1024 * 1024);
    split_w_kernel<<<wC, 256, 0, st>>>(Wo + (size_t)l * CD * CD, CD, CD, p + WOFF_WO);
    split_w_kernel<<<w1g, 256, 0, st>>>(W1 + (size_t)l * CD * FFD, CD, FFD, p + WOFF_W1);
    split_w_kernel<<<w2g, 256, 0, st>>>(W2 + (size_t)l * FFD * CD, FFD, CD, p + WOFF_W2);
}

extern "C" void kernel_launch(void* const* d_in, const int* in_sizes, int n_in,
                              void* d_out, int out_size) {
    const int*   idx  = (const int*)  d_in[0];
    const float* tok  = (const float*)d_in[1];
    const float* pos  = (const float*)d_in[2];
    const float* Wq   = (const float*)d_in[3];
    const float* Wk   = (const float*)d_in[4];
    const float* Wv   = (const float*)d_in[5];
    const float* Wo   = (const float*)d_in[6];
    const float* bo   = (const float*)d_in[7];
    const float* ln1g = (const float*)d_in[8];
    const float* ln1b = (const float*)d_in[9];
    const float* ln2g = (const float*)d_in[10];
    const float* ln2b = (const float*)d_in[11];
    const float* W1   = (const float*)d_in[12];
    const float* b1   = (const float*)d_in[13];
    const float* W2   = (const float*)d_in[14];
    const float* b2   = (const float*)d_in[15];
    const float* lnfg = (const float*)d_in[16];
    const float* lnfb = (const float*)d_in[17];
    const float* Wlm  = (const float*)d_in[18];
    const float* blm  = (const float*)d_in[19];
    float* out = (float*)d_out;

    // side stream + events (host-side objects, created once; no device memory)
    static cudaStream_t s2 = nullptr;
    static cudaEvent_t evA[NL], evB[NL];
    if (!s2) {
        cudaStreamCreateWithFlags(&s2, cudaStreamNonBlocking);
        for (int i = 0; i < NL; i++) {
            cudaEventCreateWithFlags(&evA[i], cudaEventDisableTiming);
            cudaEventCreateWithFlags(&evB[i], cudaEventDisableTiming);
        }
    }

    cudaFuncSetAttribute(tcgemm_kernel<0>,
                         cudaFuncAttributeMaxDynamicSharedMemorySize, GEMM_SMEM);
    cudaFuncSetAttribute(tcgemm_kernel<1>,
                         cudaFuncAttributeMaxDynamicSharedMemorySize, GEMM_SMEM);
    cudaFuncSetAttribute(tcgemm_kernel<2>,
                         cudaFuncAttributeMaxDynamicSharedMemorySize, GEMM_SMEM);
    cudaFuncSetAttribute(tcgemm_kernel<3>,
                         cudaFuncAttributeMaxDynamicSharedMemorySize, GEMM_SMEM);
    cudaFuncSetAttribute(attn_kernel,
                         cudaFuncAttributeMaxDynamicSharedMemorySize, ATT_SMEM);

    dim3 gC(CD / BN, NM / BM);        // (4, 32)
    dim3 gQKV(3 * CD / BN, NM / BM);  // (12, 32)
    dim3 gF(FFD / BN, NM / BM);       // (16, 32)
    dim3 gA(NB * NH, NT / 128);       // (128, 8)
    dim3 wC(CD / 32, CD / 32);
    dim3 w1g(FFD / 32, CD / 32);
    dim3 w2g(CD / 32, FFD / 32);

    // ---- layer 0 ----
    embed_kernel<<<NM, 256>>>(idx, tok, pos);
    split_w_kernel<<<wC, 256>>>(Wq, CD, CD, WOFF_QKV);
    split_w_kernel<<<wC, 256>>>(Wk, CD, CD, WOFF_QKV + 1024 * 1024);
    split_w_kernel<<<wC, 256>>>(Wv, CD, CD, WOFF_QKV + 2 * 1024 * 1024);
    ln_kernel<<<NM, 256>>>(ln1g, ln1b);
    tcgemm_kernel<3><<<gQKV, 256, GEMM_SMEM>>>(
        nullptr, 0, 0, 0, 3 * CD, CD, WOFF_QKV);
    // layer-0 Wo/W1/W2 splits: same stream, after the QKV GEMM
    split_w_kernel<<<wC, 256>>>(Wo, CD, CD, WOFF_WO);
    split_w_kernel<<<w1g, 256>>>(W1, CD, FFD, WOFF_W1);
    split_w_kernel<<<w2g, 256>>>(W2, FFD, CD, WOFF_W2);
    // fork: prefetch layer 1 weights on side stream (join at end of layer 0)
    cudaEventRecord(evA[0], 0);
    cudaStreamWaitEvent(s2, evA[0], 0);
    split_layer(1, s2, Wq, Wk, Wv, Wo, W1, W2);
    cudaEventRecord(evB[0], s2);

    attn_kernel<<<gA, 128, ATT_SMEM>>>();
    tcgemm_kernel<1><<<gC, 256, GEMM_SMEM>>>(bo, 0, 0, 0, CD, CD, WOFF_WO);
    ln_kernel<<<NM, 256>>>(ln2g, ln2b);
    tcgemm_kernel<2><<<gF, 256, GEMM_SMEM>>>(b1, 0, 0, 0, FFD, CD, WOFF_W1);
    tcgemm_kernel<1><<<gC, 256, GEMM_SMEM>>>(b2, 1, 0, 0, CD, FFD, WOFF_W2);
    cudaStreamWaitEvent(0, evB[0], 0);   // layer-1 weights ready

    // ---- layers 1..NL-1 ----
    for (int l = 1; l < NL; l++) {
        size_t p = (size_t)(l & 1) * WSEG;

        if (l + 1 < NL) {
            cudaEventRecord(evA[l], 0);
            cudaStreamWaitEvent(s2, evA[l], 0);
            split_layer(l + 1, s2, Wq, Wk, Wv, Wo, W1, W2);
            cudaEventRecord(evB[l], s2);
        }

        ln_kernel<<<NM, 256>>>(ln1g + (size_t)l * CD, ln1b + (size_t)l * CD);
        tcgemm_kernel<3><<<gQKV, 256, GEMM_SMEM>>>(
            nullptr, 0, 0, 0, 3 * CD, CD, p + WOFF_QKV);
        attn_kernel<<<gA, 128, ATT_SMEM>>>();
        tcgemm_kernel<1><<<gC, 256, GEMM_SMEM>>>(
            bo + (size_t)l * CD, 0, 0, 0, CD, CD, p + WOFF_WO);
        ln_kernel<<<NM, 256>>>(ln2g + (size_t)l * CD, ln2b + (size_t)l * CD);
        tcgemm_kernel<2><<<gF, 256, GEMM_SMEM>>>(
            b1 + (size_t)l * FFD, 0, 0, 0, FFD, CD, p + WOFF_W1);
        tcgemm_kernel<1><<<gC, 256, GEMM_SMEM>>>(
            b2 + (size_t)l * CD, 1, 0, 0, CD, FFD, p + WOFF_W2);

        if (l + 1 < NL) cudaStreamWaitEvent(0, evB[l], 0);
    }
    lm_kernel<<<NM, 128>>>(Wlm, blm, lnfg, lnfb, out);
}